// round 2
// baseline (speedup 1.0000x reference)
#include <cuda_runtime.h>
#include <math.h>

// Problem constants
#define B_   4
#define T_   2048
#define C_   2048
#define NHEAD 16
#define KHEAD 4
#define G_   4
#define H_   128
#define NH   2048   // NHEAD*H
#define KH   512    // KHEAD*H
#define M_   8192   // B*T

// Scratch (device globals; no runtime allocation allowed).
// Kernels reference these directly so kernel_launch needs no
// cudaGetSymbolAddress (keeps the captured region launches-only).
__device__ float g_q[(size_t)M_ * NH];     // 64 MB
__device__ float g_k[(size_t)M_ * KH];     // 16 MB
__device__ float g_v[(size_t)M_ * KH];     // 16 MB
__device__ float g_enc[(size_t)M_ * NH];   // 64 MB

// ---------------------------------------------------------------------------
// SGEMM: C[M,N] = A[M,K] @ B[K,N], row-major, fp32.
// 128x128 block tile, BK=8, 256 threads, 8x8 per-thread microtile.
// Requires M%128==0, N%128==0, K%8==0 (true for all four calls).
// ---------------------------------------------------------------------------
__device__ __forceinline__ void sgemm128_body(const float* __restrict__ A,
                                              const float* __restrict__ Bm,
                                              float* __restrict__ C,
                                              int M, int N, int K)
{
    __shared__ float As[8][128];   // transposed: As[k][m]
    __shared__ float Bs[8][128];   // Bs[k][n]

    const int bn = blockIdx.x * 128;
    const int bm = blockIdx.y * 128;
    const int tid = threadIdx.x;
    const int tx = tid & 15;       // 0..15 -> N
    const int ty = tid >> 4;       // 0..15 -> M

    // global load assignments
    const int arow = tid >> 1;            // 0..127
    const int ac4  = (tid & 1) * 4;       // 0 or 4
    const int brow = tid >> 5;            // 0..7
    const int bc4  = (tid & 31) * 4;      // 0..124

    const float* Ap = A + (size_t)(bm + arow) * K + ac4;
    const float* Bp = Bm + (size_t)brow * N + bn + bc4;

    float acc[8][8];
#pragma unroll
    for (int i = 0; i < 8; i++)
#pragma unroll
        for (int j = 0; j < 8; j++) acc[i][j] = 0.f;

    for (int k0 = 0; k0 < K; k0 += 8) {
        float4 av = *(const float4*)Ap;
        float4 bv = *(const float4*)Bp;
        As[ac4 + 0][arow] = av.x;
        As[ac4 + 1][arow] = av.y;
        As[ac4 + 2][arow] = av.z;
        As[ac4 + 3][arow] = av.w;
        *(float4*)&Bs[brow][bc4] = bv;
        __syncthreads();

#pragma unroll
        for (int kk = 0; kk < 8; kk++) {
            float4 a0 = *(const float4*)&As[kk][ty * 8];
            float4 a1 = *(const float4*)&As[kk][ty * 8 + 4];
            float4 b0 = *(const float4*)&Bs[kk][tx * 8];
            float4 b1 = *(const float4*)&Bs[kk][tx * 8 + 4];
            float av8[8] = {a0.x, a0.y, a0.z, a0.w, a1.x, a1.y, a1.z, a1.w};
            float bv8[8] = {b0.x, b0.y, b0.z, b0.w, b1.x, b1.y, b1.z, b1.w};
#pragma unroll
            for (int i = 0; i < 8; i++)
#pragma unroll
                for (int j = 0; j < 8; j++)
                    acc[i][j] = fmaf(av8[i], bv8[j], acc[i][j]);
        }
        __syncthreads();
        Ap += 8;
        Bp += (size_t)8 * N;
    }

#pragma unroll
    for (int i = 0; i < 8; i++) {
        float* Cp = C + (size_t)(bm + ty * 8 + i) * N + bn + tx * 8;
        *(float4*)Cp       = make_float4(acc[i][0], acc[i][1], acc[i][2], acc[i][3]);
        *(float4*)(Cp + 4) = make_float4(acc[i][4], acc[i][5], acc[i][6], acc[i][7]);
    }
}

// Four concrete GEMM entry points (scratch referenced directly).
__global__ __launch_bounds__(256) void gemm_q(const float* __restrict__ x,
                                              const float* __restrict__ Wq)
{ sgemm128_body(x, Wq, g_q, M_, NH, C_); }

__global__ __launch_bounds__(256) void gemm_k(const float* __restrict__ x,
                                              const float* __restrict__ Wk)
{ sgemm128_body(x, Wk, g_k, M_, KH, C_); }

__global__ __launch_bounds__(256) void gemm_v(const float* __restrict__ x,
                                              const float* __restrict__ Wv)
{ sgemm128_body(x, Wv, g_v, M_, KH, C_); }

__global__ __launch_bounds__(256) void gemm_o(const float* __restrict__ Wout,
                                              float* __restrict__ out)
{ sgemm128_body(g_enc, Wout, out, M_, C_, NH); }

// ---------------------------------------------------------------------------
// block reduction helper
// ---------------------------------------------------------------------------
__device__ __forceinline__ float block_reduce_sum(float v)
{
    __shared__ float red[33];
#pragma unroll
    for (int d = 16; d > 0; d >>= 1) v += __shfl_xor_sync(0xffffffffu, v, d);
    int w = threadIdx.x >> 5, l = threadIdx.x & 31;
    if (l == 0) red[w] = v;
    __syncthreads();
    int nw = blockDim.x >> 5;
    if (w == 0) {
        float s = (l < nw) ? red[l] : 0.f;
#pragma unroll
        for (int d = 16; d > 0; d >>= 1) s += __shfl_xor_sync(0xffffffffu, s, d);
        if (l == 0) red[32] = s;
    }
    __syncthreads();
    return red[32];
}

#define LN_TS (9.210340371976184f / 64.f)   // ln(10000)/64
#define QSCALE 0.08838834764831845f          // 1/sqrt(128)

// ---------------------------------------------------------------------------
// Fused rmsnorm(row of 2048) + RoPE + scale, in-place on g_q.
// one block per (b,t) row; 256 threads.
// ---------------------------------------------------------------------------
__global__ __launch_bounds__(256) void qnorm_rope()
{
    const int row = blockIdx.x;
    const int t = row & (T_ - 1);
    float* qr = g_q + (size_t)row * NH;

    float ss = 0.f;
#pragma unroll
    for (int it = 0; it < 2; it++) {
        int c = (threadIdx.x + it * 256) * 4;
        float4 v = *(const float4*)(qr + c);
        ss += v.x * v.x + v.y * v.y + v.z * v.z + v.w * v.w;
    }
    float tot = block_reduce_sum(ss);
    float rms = rsqrtf(tot * (1.f / NH) + 1e-6f);

    // 1024 half-rotate pairs (16 heads x 64)
#pragma unroll
    for (int it = 0; it < 4; it++) {
        int p = threadIdx.x + it * 256;
        int head = p >> 6;
        int hh = p & 63;
        int c1 = head * H_ + hh;
        int c2 = c1 + 64;
        float x1 = qr[c1] * rms;
        float x2 = qr[c2] * rms;
        float inv = expf(-(float)hh * LN_TS);
        float ang = (float)t * inv;
        float sa, ca;
        sincosf(ang, &sa, &ca);
        qr[c1] = (x1 * ca - x2 * sa) * QSCALE;
        qr[c2] = (x2 * ca + x1 * sa) * QSCALE;
    }
}

// same for k: row of 512, 4 heads, no scale. 128 threads.
__global__ __launch_bounds__(128) void knorm_rope()
{
    const int row = blockIdx.x;
    const int t = row & (T_ - 1);
    float* kr = g_k + (size_t)row * KH;

    int c = threadIdx.x * 4;
    float4 v = *(const float4*)(kr + c);
    float ss = v.x * v.x + v.y * v.y + v.z * v.z + v.w * v.w;
    float tot = block_reduce_sum(ss);
    float rms = rsqrtf(tot * (1.f / KH) + 1e-6f);

#pragma unroll
    for (int it = 0; it < 2; it++) {
        int p = threadIdx.x + it * 128;
        int head = p >> 6;
        int hh = p & 63;
        int c1 = head * H_ + hh;
        int c2 = c1 + 64;
        float x1 = kr[c1] * rms;
        float x2 = kr[c2] * rms;
        float inv = expf(-(float)hh * LN_TS);
        float ang = (float)t * inv;
        float sa, ca;
        sincosf(ang, &sa, &ca);
        kr[c1] = x1 * ca - x2 * sa;
        kr[c2] = x2 * ca + x1 * sa;
    }
}

// ---------------------------------------------------------------------------
// Flash attention, fp32. grid = (T/64, 16, B). block = 256 threads.
// blockIdx.y = kg = k*G+g (q head index). kv head = kg/G.
// Q/enc layout: [row = b*T+t][2048], head cols kg*128..; K/V: [row][512].
// dyn smem layout (floats):
//   Qs  [64][132]
//   Kst [128][68]   (K transposed: [h][s])
//   Vs  [64][132]
//   Ps  [64][68]
// ---------------------------------------------------------------------------
#define QS(r, c) Qs[(r) * 132 + (c)]
#define KT(h, s) Kst[(h) * 68 + (s)]
#define VS(r, c) Vs[(r) * 132 + (c)]
#define PS(r, c) Ps[(r) * 68 + (c)]
#define ATTN_SMEM ((64 * 132 + 128 * 68 + 64 * 132 + 64 * 68) * 4)

__global__ __launch_bounds__(256, 1) void attn_kernel()
{
    extern __shared__ float sm[];
    float* Qs = sm;
    float* Kst = Qs + 64 * 132;
    float* Vs = Kst + 128 * 68;
    float* Ps = Vs + 64 * 132;

    const int b = blockIdx.z;
    const int kg = blockIdx.y;
    const int kh = kg >> 2;           // G = 4
    const int t0 = blockIdx.x * 64;

    const int tid = threadIdx.x;
    const int tx = tid & 15;
    const int ty = tid >> 4;
    const int ty4 = ty * 4;
    const int tx4 = tx * 4;
    const int tx8 = tx * 8;

    const float* qbase = g_q + (size_t)(b * T_ + t0) * NH + kg * H_;
    const float* kbase = g_k + (size_t)b * T_ * KH + kh * H_;
    const float* vbase = g_v + (size_t)b * T_ * KH + kh * H_;

    // load Q tile 64x128
    for (int i = tid; i < 64 * 32; i += 256) {
        int r = i >> 5, c4 = (i & 31) * 4;
        *(float4*)&QS(r, c4) = *(const float4*)(qbase + (size_t)r * NH + c4);
    }

    float m[4], l[4];
    float acc[4][8];
#pragma unroll
    for (int i = 0; i < 4; i++) {
        m[i] = -INFINITY;
        l[i] = 0.f;
#pragma unroll
        for (int j = 0; j < 8; j++) acc[i][j] = 0.f;
    }

    for (int s0 = 0; s0 < T_; s0 += 64) {
        __syncthreads();   // protects Kst/Vs/Ps against prior-iteration readers
        // load K (transposed) and V tiles
        for (int i = tid; i < 64 * 32; i += 256) {
            int s = i >> 5, h4 = (i & 31) * 4;
            float4 kv = *(const float4*)(kbase + (size_t)(s0 + s) * KH + h4);
            KT(h4 + 0, s) = kv.x;
            KT(h4 + 1, s) = kv.y;
            KT(h4 + 2, s) = kv.z;
            KT(h4 + 3, s) = kv.w;
            *(float4*)&VS(s, h4) = *(const float4*)(vbase + (size_t)(s0 + s) * KH + h4);
        }
        __syncthreads();

        // scores: sc[i][j] = Q[ty4+i] . K[tx4+j]
        float sc[4][4];
#pragma unroll
        for (int i = 0; i < 4; i++)
#pragma unroll
            for (int j = 0; j < 4; j++) sc[i][j] = 0.f;

#pragma unroll 4
        for (int h = 0; h < H_; h += 4) {
            float4 k0 = *(const float4*)&KT(h + 0, tx4);
            float4 k1 = *(const float4*)&KT(h + 1, tx4);
            float4 k2 = *(const float4*)&KT(h + 2, tx4);
            float4 k3 = *(const float4*)&KT(h + 3, tx4);
            float kr0[4] = {k0.x, k0.y, k0.z, k0.w};
            float kr1[4] = {k1.x, k1.y, k1.z, k1.w};
            float kr2[4] = {k2.x, k2.y, k2.z, k2.w};
            float kr3[4] = {k3.x, k3.y, k3.z, k3.w};
#pragma unroll
            for (int i = 0; i < 4; i++) {
                float4 qv = *(const float4*)&QS(ty4 + i, h);
#pragma unroll
                for (int j = 0; j < 4; j++) {
                    sc[i][j] = fmaf(qv.x, kr0[j], sc[i][j]);
                    sc[i][j] = fmaf(qv.y, kr1[j], sc[i][j]);
                    sc[i][j] = fmaf(qv.z, kr2[j], sc[i][j]);
                    sc[i][j] = fmaf(qv.w, kr3[j], sc[i][j]);
                }
            }
        }

        // online softmax (row groups = 16 lanes sharing ty)
#pragma unroll
        for (int i = 0; i < 4; i++) {
            float mx = fmaxf(fmaxf(sc[i][0], sc[i][1]), fmaxf(sc[i][2], sc[i][3]));
#pragma unroll
            for (int d = 1; d < 16; d <<= 1)
                mx = fmaxf(mx, __shfl_xor_sync(0xffffffffu, mx, d));
            float mnew = fmaxf(m[i], mx);
            float corr = expf(m[i] - mnew);   // exp(-inf)=0 on first tile
            float p0 = __expf(sc[i][0] - mnew);
            float p1 = __expf(sc[i][1] - mnew);
            float p2 = __expf(sc[i][2] - mnew);
            float p3 = __expf(sc[i][3] - mnew);
            *(float4*)&PS(ty4 + i, tx4) = make_float4(p0, p1, p2, p3);
            float rs = p0 + p1 + p2 + p3;
#pragma unroll
            for (int d = 1; d < 16; d <<= 1)
                rs += __shfl_xor_sync(0xffffffffu, rs, d);
            l[i] = l[i] * corr + rs;
            m[i] = mnew;
#pragma unroll
            for (int j = 0; j < 8; j++) acc[i][j] *= corr;
        }
        __syncthreads();   // Ps visible

        // O += P @ V  (acc rows ty4+i, cols tx8..tx8+7)
#pragma unroll 2
        for (int s = 0; s < 64; s += 4) {
            float4 pv[4];
#pragma unroll
            for (int i = 0; i < 4; i++) pv[i] = *(const float4*)&PS(ty4 + i, s);
            float pr[4][4] = {{pv[0].x, pv[0].y, pv[0].z, pv[0].w},
                              {pv[1].x, pv[1].y, pv[1].z, pv[1].w},
                              {pv[2].x, pv[2].y, pv[2].z, pv[2].w},
                              {pv[3].x, pv[3].y, pv[3].z, pv[3].w}};
#pragma unroll
            for (int u = 0; u < 4; u++) {
                float4 va = *(const float4*)&VS(s + u, tx8);
                float4 vb = *(const float4*)&VS(s + u, tx8 + 4);
#pragma unroll
                for (int i = 0; i < 4; i++) {
                    acc[i][0] = fmaf(pr[i][u], va.x, acc[i][0]);
                    acc[i][1] = fmaf(pr[i][u], va.y, acc[i][1]);
                    acc[i][2] = fmaf(pr[i][u], va.z, acc[i][2]);
                    acc[i][3] = fmaf(pr[i][u], va.w, acc[i][3]);
                    acc[i][4] = fmaf(pr[i][u], vb.x, acc[i][4]);
                    acc[i][5] = fmaf(pr[i][u], vb.y, acc[i][5]);
                    acc[i][6] = fmaf(pr[i][u], vb.z, acc[i][6]);
                    acc[i][7] = fmaf(pr[i][u], vb.w, acc[i][7]);
                }
            }
        }
    }

    // epilogue: normalize and write to g_enc
#pragma unroll
    for (int i = 0; i < 4; i++) {
        float inv = 1.f / l[i];
        float* op = g_enc + (size_t)(b * T_ + t0 + ty4 + i) * NH + kg * H_ + tx8;
        *(float4*)op = make_float4(acc[i][0] * inv, acc[i][1] * inv,
                                   acc[i][2] * inv, acc[i][3] * inv);
        *(float4*)(op + 4) = make_float4(acc[i][4] * inv, acc[i][5] * inv,
                                         acc[i][6] * inv, acc[i][7] * inv);
    }
}

// ---------------------------------------------------------------------------
extern "C" void kernel_launch(void* const* d_in, const int* in_sizes, int n_in,
                              void* d_out, int out_size)
{
    const float* x    = (const float*)d_in[0];
    const float* Wq   = (const float*)d_in[1];
    const float* Wk   = (const float*)d_in[2];
    const float* Wv   = (const float*)d_in[3];
    const float* Wout = (const float*)d_in[4];
    float* out = (float*)d_out;

    (void)cudaFuncSetAttribute(attn_kernel,
                               cudaFuncAttributeMaxDynamicSharedMemorySize,
                               ATTN_SMEM);

    // projections
    gemm_q<<<dim3(NH / 128, M_ / 128), 256>>>(x, Wq);
    gemm_k<<<dim3(KH / 128, M_ / 128), 256>>>(x, Wk);
    gemm_v<<<dim3(KH / 128, M_ / 128), 256>>>(x, Wv);

    // norms + rope
    qnorm_rope<<<M_, 256>>>();
    knorm_rope<<<M_, 128>>>();

    // attention
    attn_kernel<<<dim3(T_ / 64, NHEAD, B_), 256, ATTN_SMEM>>>();

    // output projection
    gemm_o<<<dim3(C_ / 128, M_ / 128), 256>>>(Wout, out);
}

// round 10
// speedup vs baseline: 1.3043x; 1.3043x over previous
#include <cuda_runtime.h>
#include <cuda_bf16.h>
#include <math.h>
#include <stdint.h>

// Problem constants
#define B_   4
#define T_   2048
#define C_   2048
#define NHEAD 16
#define KHEAD 4
#define H_   128
#define NH   2048   // NHEAD*H
#define KH   512    // KHEAD*H
#define M_   8192   // B*T
#define KTOT 2048   // K dim of every projection GEMM

// fp32 scratch (device globals; referenced ONLY from device code)
__device__ float g_q[(size_t)M_ * NH];     // 64 MB
__device__ float g_k[(size_t)M_ * KH];     // 16 MB
__device__ float g_v[(size_t)M_ * KH];     // 16 MB
__device__ float g_enc[(size_t)M_ * NH];   // 64 MB

// bf16 hi/lo split scratch
__device__ __nv_bfloat16 g_xh[(size_t)M_ * C_], g_xl[(size_t)M_ * C_];
__device__ __nv_bfloat16 g_wqt_h[(size_t)NH * C_], g_wqt_l[(size_t)NH * C_];
__device__ __nv_bfloat16 g_wkt_h[(size_t)KH * C_], g_wkt_l[(size_t)KH * C_];
__device__ __nv_bfloat16 g_wvt_h[(size_t)KH * C_], g_wvt_l[(size_t)KH * C_];
__device__ __nv_bfloat16 g_wot_h[(size_t)C_ * NH], g_wot_l[(size_t)C_ * NH];
__device__ __nv_bfloat16 g_ech[(size_t)M_ * NH], g_ecl[(size_t)M_ * NH];

// ---------------------------------------------------------------------------
// helpers
// ---------------------------------------------------------------------------
__device__ __forceinline__ uint32_t smem_u32(const void* p)
{
    uint32_t a;
    asm("{ .reg .u64 t; cvta.to.shared.u64 t, %1; cvt.u32.u64 %0, t; }"
        : "=r"(a) : "l"(p));
    return a;
}

__device__ __forceinline__ void cp16(uint32_t dst, const void* src)
{
    asm volatile("cp.async.cg.shared.global [%0], [%1], 16;"
                 :: "r"(dst), "l"(src) : "memory");
}

// ---------------------------------------------------------------------------
// bf16x3 GEMM on mma.sync: C[M,Ntot] = Ah@Bh^T + Ah@Bl^T + Al@Bh^T
// A*: [M,2048] row-major bf16.  B*: [Ntot,2048] row-major bf16 (transposed W).
// CTA 128x128, BK=32, 8 warps (warp tile 64x32), 4-stage cp.async pipeline.
// Virtual K = 3*2048 -> 192 chunks with per-segment pointer select.
// smem: padded rows of 40 bf16 (80 B).  Fragments loaded directly per the
// documented m16n8k16 layout (no ldmatrix).
// ---------------------------------------------------------------------------
#define NCHUNK   192
#define ROWW32   20                    // padded row width in 32-bit words
#define STAGE_B  20480                 // bytes per stage (2 * 128*80)
#define STAGE_W  5120                  // words per stage
#define BTILE_W  2560                  // word offset of B tile within stage
#define MG_SMEM  (4 * STAGE_B)         // 81920

__device__ __forceinline__ void mgemm_body(const __nv_bfloat16* __restrict__ Ah,
                                           const __nv_bfloat16* __restrict__ Al,
                                           const __nv_bfloat16* __restrict__ Bh,
                                           const __nv_bfloat16* __restrict__ Bl,
                                           float* __restrict__ C, int Ntot)
{
    extern __shared__ char smx[];
    const uint32_t sb = smem_u32(smx);
    const uint32_t* s32 = (const uint32_t*)smx;
    const int tid = threadIdx.x;
    const int bm = blockIdx.y * 128, bn = blockIdx.x * 128;
    const int w = tid >> 5, lane = tid & 31;
    const int m0 = (w >> 2) * 64, n0 = (w & 3) * 32;
    const int grp = lane >> 2, tg = lane & 3;

    float acc[4][4][4];
#pragma unroll
    for (int mt = 0; mt < 4; mt++)
#pragma unroll
        for (int nt = 0; nt < 4; nt++)
#pragma unroll
            for (int r = 0; r < 4; r++) acc[mt][nt][r] = 0.f;

    auto load_stage = [&](int c) {
        const int stage = c & 3;
        const int seg = c >> 6;
        const int kk = (c & 63) << 5;
        const __nv_bfloat16* A = (seg < 2) ? Ah : Al;
        const __nv_bfloat16* Bp = (seg == 1) ? Bl : Bh;
        const uint32_t abase = sb + stage * STAGE_B;
        const uint32_t bbase = abase + BTILE_W * 4;
#pragma unroll
        for (int i = 0; i < 2; i++) {
            int u = tid + (i << 8);         // 0..511
            int row = u >> 2, k16 = u & 3;  // k16 = 16-byte unit (8 bf16)
            uint32_t so = (uint32_t)(row * 80 + k16 * 16);
            cp16(abase + so, A + (size_t)(bm + row) * KTOT + kk + k16 * 8);
            cp16(bbase + so, Bp + (size_t)(bn + row) * KTOT + kk + k16 * 8);
        }
        asm volatile("cp.async.commit_group;" ::: "memory");
    };

    load_stage(0);
    load_stage(1);
    load_stage(2);

    for (int c = 0; c < NCHUNK; c++) {
        asm volatile("cp.async.wait_group 2;" ::: "memory");   // chunk c landed
        __syncthreads();
        if (c + 3 < NCHUNK) load_stage(c + 3);
        else asm volatile("cp.async.commit_group;" ::: "memory");

        const int wstg = (c & 3) * STAGE_W;
#pragma unroll
        for (int ks = 0; ks < 2; ks++) {
            // documented m16n8k16 fragment layout, loaded directly:
            // a0=A[grp][kp] a1=A[grp+8][kp] a2=A[grp][kp+8] a3=A[grp+8][kp+8]
            // b0=Bs[n=grp][kp] b1=Bs[grp][kp+8]   (kp = ks*16 + tg*2)
            const int wk = ks * 8 + tg;
            uint32_t a[4][4], b[4][2];
#pragma unroll
            for (int mt = 0; mt < 4; mt++) {
                int base = wstg + (m0 + mt * 16 + grp) * ROWW32 + wk;
                a[mt][0] = s32[base];
                a[mt][1] = s32[base + 8 * ROWW32];
                a[mt][2] = s32[base + 4];
                a[mt][3] = s32[base + 8 * ROWW32 + 4];
            }
#pragma unroll
            for (int nt = 0; nt < 4; nt++) {
                int base = wstg + BTILE_W + (n0 + nt * 8 + grp) * ROWW32 + wk;
                b[nt][0] = s32[base];
                b[nt][1] = s32[base + 4];
            }
#pragma unroll
            for (int mt = 0; mt < 4; mt++)
#pragma unroll
                for (int nt = 0; nt < 4; nt++) {
                    asm volatile(
                        "mma.sync.aligned.m16n8k16.row.col.f32.bf16.bf16.f32 "
                        "{%0,%1,%2,%3}, {%4,%5,%6,%7}, {%8,%9}, {%0,%1,%2,%3};"
                        : "+f"(acc[mt][nt][0]), "+f"(acc[mt][nt][1]),
                          "+f"(acc[mt][nt][2]), "+f"(acc[mt][nt][3])
                        : "r"(a[mt][0]), "r"(a[mt][1]), "r"(a[mt][2]), "r"(a[mt][3]),
                          "r"(b[nt][0]), "r"(b[nt][1]));
                }
        }
    }

    // epilogue: c0,c1 -> (row grp, cols tg*2,+1); c2,c3 -> row grp+8
#pragma unroll
    for (int mt = 0; mt < 4; mt++)
#pragma unroll
        for (int nt = 0; nt < 4; nt++) {
            float* cp0 = C + (size_t)(bm + m0 + mt * 16 + grp) * Ntot
                           + bn + n0 + nt * 8 + tg * 2;
            *(float2*)cp0 = make_float2(acc[mt][nt][0], acc[mt][nt][1]);
            *(float2*)(cp0 + (size_t)8 * Ntot) =
                make_float2(acc[mt][nt][2], acc[mt][nt][3]);
        }
}

// Wrappers: device-side references to the scratch globals (LEGAL in device
// code; passing the symbols from host code silently reads host-shadow zeros
// on GB300 ATS — the bug that produced rel_err=1.0 in R5-R9).
__global__ __launch_bounds__(256) void mgemm_q()
{ mgemm_body(g_xh, g_xl, g_wqt_h, g_wqt_l, g_q, NH); }

__global__ __launch_bounds__(256) void mgemm_k()
{ mgemm_body(g_xh, g_xl, g_wkt_h, g_wkt_l, g_k, KH); }

__global__ __launch_bounds__(256) void mgemm_v()
{ mgemm_body(g_xh, g_xl, g_wvt_h, g_wvt_l, g_v, KH); }

__global__ __launch_bounds__(256) void mgemm_o(float* __restrict__ out)
{ mgemm_body(g_ech, g_ecl, g_wot_h, g_wot_l, out, C_); }

// ---------------------------------------------------------------------------
// fp32 -> bf16 hi/lo split (wrappers bind the device globals)
// ---------------------------------------------------------------------------
__device__ __forceinline__ void split_body(const float* __restrict__ s,
                                           __nv_bfloat16* __restrict__ h,
                                           __nv_bfloat16* __restrict__ l,
                                           int n4)
{
    int i = blockIdx.x * 256 + threadIdx.x;
    if (i >= n4) return;
    float4 v = ((const float4*)s)[i];
    __nv_bfloat16 h0 = __float2bfloat16(v.x), h1 = __float2bfloat16(v.y);
    __nv_bfloat16 h2 = __float2bfloat16(v.z), h3 = __float2bfloat16(v.w);
    __nv_bfloat16 l0 = __float2bfloat16(v.x - __bfloat162float(h0));
    __nv_bfloat16 l1 = __float2bfloat16(v.y - __bfloat162float(h1));
    __nv_bfloat16 l2 = __float2bfloat16(v.z - __bfloat162float(h2));
    __nv_bfloat16 l3 = __float2bfloat16(v.w - __bfloat162float(h3));
    ((__nv_bfloat162*)h)[2 * i]     = __nv_bfloat162(h0, h1);
    ((__nv_bfloat162*)h)[2 * i + 1] = __nv_bfloat162(h2, h3);
    ((__nv_bfloat162*)l)[2 * i]     = __nv_bfloat162(l0, l1);
    ((__nv_bfloat162*)l)[2 * i + 1] = __nv_bfloat162(l2, l3);
}

__global__ __launch_bounds__(256) void split_x(const float* __restrict__ x)
{ split_body(x, g_xh, g_xl, M_ * C_ / 4); }

__global__ __launch_bounds__(256) void split_enc()
{ split_body(g_enc, g_ech, g_ecl, M_ * NH / 4); }

// ---------------------------------------------------------------------------
// transpose + split: src[R][Cc] fp32 -> dh/dl[Cc][R] bf16
// block (32,8), grid (Cc/32, R/32)
// ---------------------------------------------------------------------------
__device__ __forceinline__ void tsp_body(const float* __restrict__ src,
                                         __nv_bfloat16* __restrict__ dh,
                                         __nv_bfloat16* __restrict__ dl,
                                         int R, int Cc)
{
    __shared__ float tile[32][33];
    const int c0 = blockIdx.x * 32, r0 = blockIdx.y * 32;
    const int tx = threadIdx.x, ty = threadIdx.y;
#pragma unroll
    for (int i = 0; i < 4; i++)
        tile[ty + i * 8][tx] = src[(size_t)(r0 + ty + i * 8) * Cc + c0 + tx];
    __syncthreads();
#pragma unroll
    for (int i = 0; i < 4; i++) {
        float v = tile[tx][ty + i * 8];
        __nv_bfloat16 h = __float2bfloat16(v);
        __nv_bfloat16 l = __float2bfloat16(v - __bfloat162float(h));
        size_t o = (size_t)(c0 + ty + i * 8) * R + r0 + tx;
        dh[o] = h;
        dl[o] = l;
    }
}

__global__ void tsp_q(const float* __restrict__ Wq)
{ tsp_body(Wq, g_wqt_h, g_wqt_l, C_, NH); }
__global__ void tsp_k(const float* __restrict__ Wk)
{ tsp_body(Wk, g_wkt_h, g_wkt_l, C_, KH); }
__global__ void tsp_v(const float* __restrict__ Wv)
{ tsp_body(Wv, g_wvt_h, g_wvt_l, C_, KH); }
__global__ void tsp_o(const float* __restrict__ Wout)
{ tsp_body(Wout, g_wot_h, g_wot_l, NH, C_); }

// ---------------------------------------------------------------------------
// block reduction helper
// ---------------------------------------------------------------------------
__device__ __forceinline__ float block_reduce_sum(float v)
{
    __shared__ float red[33];
#pragma unroll
    for (int d = 16; d > 0; d >>= 1) v += __shfl_xor_sync(0xffffffffu, v, d);
    int w = threadIdx.x >> 5, l = threadIdx.x & 31;
    if (l == 0) red[w] = v;
    __syncthreads();
    int nw = blockDim.x >> 5;
    if (w == 0) {
        float s = (l < nw) ? red[l] : 0.f;
#pragma unroll
        for (int d = 16; d > 0; d >>= 1) s += __shfl_xor_sync(0xffffffffu, s, d);
        if (l == 0) red[32] = s;
    }
    __syncthreads();
    return red[32];
}

#define LN_TS (9.210340371976184f / 64.f)   // ln(10000)/64
#define QSCALE 0.08838834764831845f          // 1/sqrt(128)

__global__ __launch_bounds__(256) void qnorm_rope()
{
    const int row = blockIdx.x;
    const int t = row & (T_ - 1);
    float* qr = g_q + (size_t)row * NH;

    float ss = 0.f;
#pragma unroll
    for (int it = 0; it < 2; it++) {
        int c = (threadIdx.x + it * 256) * 4;
        float4 v = *(const float4*)(qr + c);
        ss += v.x * v.x + v.y * v.y + v.z * v.z + v.w * v.w;
    }
    float tot = block_reduce_sum(ss);
    float rms = rsqrtf(tot * (1.f / NH) + 1e-6f);

#pragma unroll
    for (int it = 0; it < 4; it++) {
        int p = threadIdx.x + it * 256;
        int head = p >> 6;
        int hh = p & 63;
        int c1 = head * H_ + hh;
        int c2 = c1 + 64;
        float x1 = qr[c1] * rms;
        float x2 = qr[c2] * rms;
        float inv = expf(-(float)hh * LN_TS);
        float ang = (float)t * inv;
        float sa, ca;
        sincosf(ang, &sa, &ca);
        qr[c1] = (x1 * ca - x2 * sa) * QSCALE;
        qr[c2] = (x2 * ca + x1 * sa) * QSCALE;
    }
}

__global__ __launch_bounds__(128) void knorm_rope()
{
    const int row = blockIdx.x;
    const int t = row & (T_ - 1);
    float* kr = g_k + (size_t)row * KH;

    int c = threadIdx.x * 4;
    float4 v = *(const float4*)(kr + c);
    float ss = v.x * v.x + v.y * v.y + v.z * v.z + v.w * v.w;
    float tot = block_reduce_sum(ss);
    float rms = rsqrtf(tot * (1.f / KH) + 1e-6f);

#pragma unroll
    for (int it = 0; it < 2; it++) {
        int p = threadIdx.x + it * 128;
        int head = p >> 6;
        int hh = p & 63;
        int c1 = head * H_ + hh;
        int c2 = c1 + 64;
        float x1 = kr[c1] * rms;
        float x2 = kr[c2] * rms;
        float inv = expf(-(float)hh * LN_TS);
        float ang = (float)t * inv;
        float sa, ca;
        sincosf(ang, &sa, &ca);
        kr[c1] = x1 * ca - x2 * sa;
        kr[c2] = x2 * ca + x1 * sa;
    }
}

// ---------------------------------------------------------------------------
// Flash attention, fp32 SIMT (proven in R2)
// ---------------------------------------------------------------------------
#define QS(r, c) Qs[(r) * 132 + (c)]
#define KT(h, s) Kst[(h) * 68 + (s)]
#define VS(r, c) Vs[(r) * 132 + (c)]
#define PS(r, c) Ps[(r) * 68 + (c)]
#define ATTN_SMEM ((64 * 132 + 128 * 68 + 64 * 132 + 64 * 68) * 4)

__global__ __launch_bounds__(256, 1) void attn_kernel()
{
    extern __shared__ float sm[];
    float* Qs = sm;
    float* Kst = Qs + 64 * 132;
    float* Vs = Kst + 128 * 68;
    float* Ps = Vs + 64 * 132;

    const int b = blockIdx.z;
    const int kg = blockIdx.y;
    const int kh = kg >> 2;
    const int t0 = blockIdx.x * 64;

    const int tid = threadIdx.x;
    const int tx = tid & 15;
    const int ty = tid >> 4;
    const int ty4 = ty * 4;
    const int tx4 = tx * 4;
    const int tx8 = tx * 8;

    const float* qbase = g_q + (size_t)(b * T_ + t0) * NH + kg * H_;
    const float* kbase = g_k + (size_t)b * T_ * KH + kh * H_;
    const float* vbase = g_v + (size_t)b * T_ * KH + kh * H_;

    for (int i = tid; i < 64 * 32; i += 256) {
        int r = i >> 5, c4 = (i & 31) * 4;
        *(float4*)&QS(r, c4) = *(const float4*)(qbase + (size_t)r * NH + c4);
    }

    float m[4], l[4];
    float acc[4][8];
#pragma unroll
    for (int i = 0; i < 4; i++) {
        m[i] = -INFINITY;
        l[i] = 0.f;
#pragma unroll
        for (int j = 0; j < 8; j++) acc[i][j] = 0.f;
    }

    for (int s0 = 0; s0 < T_; s0 += 64) {
        __syncthreads();
        for (int i = tid; i < 64 * 32; i += 256) {
            int s = i >> 5, h4 = (i & 31) * 4;
            float4 kv = *(const float4*)(kbase + (size_t)(s0 + s) * KH + h4);
            KT(h4 + 0, s) = kv.x;
            KT(h4 + 1, s) = kv.y;
            KT(h4 + 2, s) = kv.z;
            KT(h4 + 3, s) = kv.w;
            *(float4*)&VS(s, h4) = *(const float4*)(vbase + (size_t)(s0 + s) * KH + h4);
        }
        __syncthreads();

        float sc[4][4];
#pragma unroll
        for (int i = 0; i < 4; i++)
#pragma unroll
            for (int j = 0; j < 4; j++) sc[i][j] = 0.f;

#pragma unroll 4
        for (int h = 0; h < H_; h += 4) {
            float4 k0 = *(const float4*)&KT(h + 0, tx4);
            float4 k1 = *(const float4*)&KT(h + 1, tx4);
            float4 k2 = *(const float4*)&KT(h + 2, tx4);
            float4 k3 = *(const float4*)&KT(h + 3, tx4);
            float kr0[4] = {k0.x, k0.y, k0.z, k0.w};
            float kr1[4] = {k1.x, k1.y, k1.z, k1.w};
            float kr2[4] = {k2.x, k2.y, k2.z, k2.w};
            float kr3[4] = {k3.x, k3.y, k3.z, k3.w};
#pragma unroll
            for (int i = 0; i < 4; i++) {
                float4 qv = *(const float4*)&QS(ty4 + i, h);
#pragma unroll
                for (int j = 0; j < 4; j++) {
                    sc[i][j] = fmaf(qv.x, kr0[j], sc[i][j]);
                    sc[i][j] = fmaf(qv.y, kr1[j], sc[i][j]);
                    sc[i][j] = fmaf(qv.z, kr2[j], sc[i][j]);
                    sc[i][j] = fmaf(qv.w, kr3[j], sc[i][j]);
                }
            }
        }

#pragma unroll
        for (int i = 0; i < 4; i++) {
            float mx = fmaxf(fmaxf(sc[i][0], sc[i][1]), fmaxf(sc[i][2], sc[i][3]));
#pragma unroll
            for (int d = 1; d < 16; d <<= 1)
                mx = fmaxf(mx, __shfl_xor_sync(0xffffffffu, mx, d));
            float mnew = fmaxf(m[i], mx);
            float corr = expf(m[i] - mnew);
            float p0 = __expf(sc[i][0] - mnew);
            float p1 = __expf(sc[i][1] - mnew);
            float p2 = __expf(sc[i][2] - mnew);
            float p3 = __expf(sc[i][3] - mnew);
            *(float4*)&PS(ty4 + i, tx4) = make_float4(p0, p1, p2, p3);
            float rs = p0 + p1 + p2 + p3;
#pragma unroll
            for (int d = 1; d < 16; d <<= 1)
                rs += __shfl_xor_sync(0xffffffffu, rs, d);
            l[i] = l[i] * corr + rs;
            m[i] = mnew;
#pragma unroll
            for (int j = 0; j < 8; j++) acc[i][j] *= corr;
        }
        __syncthreads();

#pragma unroll 2
        for (int s = 0; s < 64; s += 4) {
            float4 pv[4];
#pragma unroll
            for (int i = 0; i < 4; i++) pv[i] = *(const float4*)&PS(ty4 + i, s);
            float pr[4][4] = {{pv[0].x, pv[0].y, pv[0].z, pv[0].w},
                              {pv[1].x, pv[1].y, pv[1].z, pv[1].w},
                              {pv[2].x, pv[2].y, pv[2].z, pv[2].w},
                              {pv[3].x, pv[3].y, pv[3].z, pv[3].w}};
#pragma unroll
            for (int u = 0; u < 4; u++) {
                float4 va = *(const float4*)&VS(s + u, tx8);
                float4 vb = *(const float4*)&VS(s + u, tx8 + 4);
#pragma unroll
                for (int i = 0; i < 4; i++) {
                    acc[i][0] = fmaf(pr[i][u], va.x, acc[i][0]);
                    acc[i][1] = fmaf(pr[i][u], va.y, acc[i][1]);
                    acc[i][2] = fmaf(pr[i][u], va.z, acc[i][2]);
                    acc[i][3] = fmaf(pr[i][u], va.w, acc[i][3]);
                    acc[i][4] = fmaf(pr[i][u], vb.x, acc[i][4]);
                    acc[i][5] = fmaf(pr[i][u], vb.y, acc[i][5]);
                    acc[i][6] = fmaf(pr[i][u], vb.z, acc[i][6]);
                    acc[i][7] = fmaf(pr[i][u], vb.w, acc[i][7]);
                }
            }
        }
    }

#pragma unroll
    for (int i = 0; i < 4; i++) {
        float inv = 1.f / l[i];
        float* op = g_enc + (size_t)(b * T_ + t0 + ty4 + i) * NH + kg * H_ + tx8;
        *(float4*)op = make_float4(acc[i][0] * inv, acc[i][1] * inv,
                                   acc[i][2] * inv, acc[i][3] * inv);
        *(float4*)(op + 4) = make_float4(acc[i][4] * inv, acc[i][5] * inv,
                                         acc[i][6] * inv, acc[i][7] * inv);
    }
}

// ---------------------------------------------------------------------------
extern "C" void kernel_launch(void* const* d_in, const int* in_sizes, int n_in,
                              void* d_out, int out_size)
{
    const float* x    = (const float*)d_in[0];
    const float* Wq   = (const float*)d_in[1];
    const float* Wk   = (const float*)d_in[2];
    const float* Wv   = (const float*)d_in[3];
    const float* Wout = (const float*)d_in[4];
    float* out = (float*)d_out;

    (void)cudaFuncSetAttribute(attn_kernel,
                               cudaFuncAttributeMaxDynamicSharedMemorySize, ATTN_SMEM);
    (void)cudaFuncSetAttribute(mgemm_q,
                               cudaFuncAttributeMaxDynamicSharedMemorySize, MG_SMEM);
    (void)cudaFuncSetAttribute(mgemm_k,
                               cudaFuncAttributeMaxDynamicSharedMemorySize, MG_SMEM);
    (void)cudaFuncSetAttribute(mgemm_v,
                               cudaFuncAttributeMaxDynamicSharedMemorySize, MG_SMEM);
    (void)cudaFuncSetAttribute(mgemm_o,
                               cudaFuncAttributeMaxDynamicSharedMemorySize, MG_SMEM);

    // split x into bf16 hi/lo
    split_x<<<M_ * C_ / 4 / 256, 256>>>(x);

    // transpose + split weights: W[K,N] -> Wt[N,K]
    tsp_q<<<dim3(NH / 32, C_ / 32), dim3(32, 8)>>>(Wq);
    tsp_k<<<dim3(KH / 32, C_ / 32), dim3(32, 8)>>>(Wk);
    tsp_v<<<dim3(KH / 32, C_ / 32), dim3(32, 8)>>>(Wv);
    tsp_o<<<dim3(C_ / 32, NH / 32), dim3(32, 8)>>>(Wout);

    // projections on tensor cores (mma.sync bf16x3)
    mgemm_q<<<dim3(NH / 128, M_ / 128), 256, MG_SMEM>>>();
    mgemm_k<<<dim3(KH / 128, M_ / 128), 256, MG_SMEM>>>();
    mgemm_v<<<dim3(KH / 128, M_ / 128), 256, MG_SMEM>>>();

    // norms + rope
    qnorm_rope<<<M_, 256>>>();
    knorm_rope<<<M_, 128>>>();

    // attention (fp32 SIMT)
    attn_kernel<<<dim3(T_ / 64, NHEAD, B_), 256, ATTN_SMEM>>>();

    // out projection
    split_enc<<<M_ * NH / 4 / 256, 256>>>();
    mgemm_o<<<dim3(C_ / 128, M_ / 128), 256, MG_SMEM>>>(out);
}

// round 11
// speedup vs baseline: 2.4483x; 1.8771x over previous
#include <cuda_runtime.h>
#include <cuda_bf16.h>
#include <math.h>
#include <stdint.h>

// Problem constants
#define B_   4
#define T_   2048
#define C_   2048
#define NHEAD 16
#define KHEAD 4
#define H_   128
#define NH   2048   // NHEAD*H
#define KH   512    // KHEAD*H
#define M_   8192   // B*T
#define KTOT 2048   // K dim of every projection GEMM

// fp32 scratch (device globals; referenced ONLY from device code)
__device__ float g_q[(size_t)M_ * NH];     // q proj out (pre-norm)
__device__ float g_k[(size_t)M_ * KH];
__device__ float g_v[(size_t)M_ * KH];

// bf16 hi/lo split scratch
__device__ __nv_bfloat16 g_xh[(size_t)M_ * C_], g_xl[(size_t)M_ * C_];
__device__ __nv_bfloat16 g_wqt_h[(size_t)NH * C_], g_wqt_l[(size_t)NH * C_];
__device__ __nv_bfloat16 g_wkt_h[(size_t)KH * C_], g_wkt_l[(size_t)KH * C_];
__device__ __nv_bfloat16 g_wvt_h[(size_t)KH * C_], g_wvt_l[(size_t)KH * C_];
__device__ __nv_bfloat16 g_wot_h[(size_t)C_ * NH], g_wot_l[(size_t)C_ * NH];
__device__ __nv_bfloat16 g_ech[(size_t)M_ * NH], g_ecl[(size_t)M_ * NH];
// post-norm/rope q,k and v in bf16 hi/lo for tensor-core attention
__device__ __nv_bfloat16 g_qh[(size_t)M_ * NH], g_ql[(size_t)M_ * NH];
__device__ __nv_bfloat16 g_kh[(size_t)M_ * KH], g_kl[(size_t)M_ * KH];
__device__ __nv_bfloat16 g_vh[(size_t)M_ * KH], g_vl[(size_t)M_ * KH];

// ---------------------------------------------------------------------------
// helpers
// ---------------------------------------------------------------------------
__device__ __forceinline__ uint32_t smem_u32(const void* p)
{
    uint32_t a;
    asm("{ .reg .u64 t; cvta.to.shared.u64 t, %1; cvt.u32.u64 %0, t; }"
        : "=r"(a) : "l"(p));
    return a;
}

__device__ __forceinline__ void cp16(uint32_t dst, const void* src)
{
    asm volatile("cp.async.cg.shared.global [%0], [%1], 16;"
                 :: "r"(dst), "l"(src) : "memory");
}

#define MMA16816(acc, a0, a1, a2, a3, b0, b1)                                  \
    asm volatile(                                                              \
        "mma.sync.aligned.m16n8k16.row.col.f32.bf16.bf16.f32 "                 \
        "{%0,%1,%2,%3}, {%4,%5,%6,%7}, {%8,%9}, {%0,%1,%2,%3};"                \
        : "+f"((acc)[0]), "+f"((acc)[1]), "+f"((acc)[2]), "+f"((acc)[3])       \
        : "r"(a0), "r"(a1), "r"(a2), "r"(a3), "r"(b0), "r"(b1))

// ---------------------------------------------------------------------------
// bf16x3 GEMM on mma.sync (proven in R10): C = Ah@Bh^T + Ah@Bl^T + Al@Bh^T
// ---------------------------------------------------------------------------
#define NCHUNK   192
#define ROWW32   20
#define STAGE_B  20480
#define STAGE_W  5120
#define BTILE_W  2560
#define MG_SMEM  (4 * STAGE_B)

__device__ __forceinline__ void mgemm_body(const __nv_bfloat16* __restrict__ Ah,
                                           const __nv_bfloat16* __restrict__ Al,
                                           const __nv_bfloat16* __restrict__ Bh,
                                           const __nv_bfloat16* __restrict__ Bl,
                                           float* __restrict__ C, int Ntot)
{
    extern __shared__ char smx[];
    const uint32_t sb = smem_u32(smx);
    const uint32_t* s32 = (const uint32_t*)smx;
    const int tid = threadIdx.x;
    const int bm = blockIdx.y * 128, bn = blockIdx.x * 128;
    const int w = tid >> 5, lane = tid & 31;
    const int m0 = (w >> 2) * 64, n0 = (w & 3) * 32;
    const int grp = lane >> 2, tg = lane & 3;

    float acc[4][4][4];
#pragma unroll
    for (int mt = 0; mt < 4; mt++)
#pragma unroll
        for (int nt = 0; nt < 4; nt++)
#pragma unroll
            for (int r = 0; r < 4; r++) acc[mt][nt][r] = 0.f;

    auto load_stage = [&](int c) {
        const int stage = c & 3;
        const int seg = c >> 6;
        const int kk = (c & 63) << 5;
        const __nv_bfloat16* A = (seg < 2) ? Ah : Al;
        const __nv_bfloat16* Bp = (seg == 1) ? Bl : Bh;
        const uint32_t abase = sb + stage * STAGE_B;
        const uint32_t bbase = abase + BTILE_W * 4;
#pragma unroll
        for (int i = 0; i < 2; i++) {
            int u = tid + (i << 8);
            int row = u >> 2, k16 = u & 3;
            uint32_t so = (uint32_t)(row * 80 + k16 * 16);
            cp16(abase + so, A + (size_t)(bm + row) * KTOT + kk + k16 * 8);
            cp16(bbase + so, Bp + (size_t)(bn + row) * KTOT + kk + k16 * 8);
        }
        asm volatile("cp.async.commit_group;" ::: "memory");
    };

    load_stage(0);
    load_stage(1);
    load_stage(2);

    for (int c = 0; c < NCHUNK; c++) {
        asm volatile("cp.async.wait_group 2;" ::: "memory");
        __syncthreads();
        if (c + 3 < NCHUNK) load_stage(c + 3);
        else asm volatile("cp.async.commit_group;" ::: "memory");

        const int wstg = (c & 3) * STAGE_W;
#pragma unroll
        for (int ks = 0; ks < 2; ks++) {
            const int wk = ks * 8 + tg;
            uint32_t a[4][4], b[4][2];
#pragma unroll
            for (int mt = 0; mt < 4; mt++) {
                int base = wstg + (m0 + mt * 16 + grp) * ROWW32 + wk;
                a[mt][0] = s32[base];
                a[mt][1] = s32[base + 8 * ROWW32];
                a[mt][2] = s32[base + 4];
                a[mt][3] = s32[base + 8 * ROWW32 + 4];
            }
#pragma unroll
            for (int nt = 0; nt < 4; nt++) {
                int base = wstg + BTILE_W + (n0 + nt * 8 + grp) * ROWW32 + wk;
                b[nt][0] = s32[base];
                b[nt][1] = s32[base + 4];
            }
#pragma unroll
            for (int mt = 0; mt < 4; mt++)
#pragma unroll
                for (int nt = 0; nt < 4; nt++)
                    MMA16816(acc[mt][nt], a[mt][0], a[mt][1], a[mt][2], a[mt][3],
                             b[nt][0], b[nt][1]);
        }
    }

#pragma unroll
    for (int mt = 0; mt < 4; mt++)
#pragma unroll
        for (int nt = 0; nt < 4; nt++) {
            float* cp0 = C + (size_t)(bm + m0 + mt * 16 + grp) * Ntot
                           + bn + n0 + nt * 8 + tg * 2;
            *(float2*)cp0 = make_float2(acc[mt][nt][0], acc[mt][nt][1]);
            *(float2*)(cp0 + (size_t)8 * Ntot) =
                make_float2(acc[mt][nt][2], acc[mt][nt][3]);
        }
}

__global__ __launch_bounds__(256) void mgemm_q()
{ mgemm_body(g_xh, g_xl, g_wqt_h, g_wqt_l, g_q, NH); }
__global__ __launch_bounds__(256) void mgemm_k()
{ mgemm_body(g_xh, g_xl, g_wkt_h, g_wkt_l, g_k, KH); }
__global__ __launch_bounds__(256) void mgemm_v()
{ mgemm_body(g_xh, g_xl, g_wvt_h, g_wvt_l, g_v, KH); }
__global__ __launch_bounds__(256) void mgemm_o(float* __restrict__ out)
{ mgemm_body(g_ech, g_ecl, g_wot_h, g_wot_l, out, C_); }

// ---------------------------------------------------------------------------
// fp32 -> bf16 hi/lo split
// ---------------------------------------------------------------------------
__device__ __forceinline__ void split_body(const float* __restrict__ s,
                                           __nv_bfloat16* __restrict__ h,
                                           __nv_bfloat16* __restrict__ l,
                                           int n4)
{
    int i = blockIdx.x * 256 + threadIdx.x;
    if (i >= n4) return;
    float4 v = ((const float4*)s)[i];
    __nv_bfloat16 h0 = __float2bfloat16(v.x), h1 = __float2bfloat16(v.y);
    __nv_bfloat16 h2 = __float2bfloat16(v.z), h3 = __float2bfloat16(v.w);
    __nv_bfloat16 l0 = __float2bfloat16(v.x - __bfloat162float(h0));
    __nv_bfloat16 l1 = __float2bfloat16(v.y - __bfloat162float(h1));
    __nv_bfloat16 l2 = __float2bfloat16(v.z - __bfloat162float(h2));
    __nv_bfloat16 l3 = __float2bfloat16(v.w - __bfloat162float(h3));
    ((__nv_bfloat162*)h)[2 * i]     = __nv_bfloat162(h0, h1);
    ((__nv_bfloat162*)h)[2 * i + 1] = __nv_bfloat162(h2, h3);
    ((__nv_bfloat162*)l)[2 * i]     = __nv_bfloat162(l0, l1);
    ((__nv_bfloat162*)l)[2 * i + 1] = __nv_bfloat162(l2, l3);
}

__global__ __launch_bounds__(256) void split_x(const float* __restrict__ x)
{ split_body(x, g_xh, g_xl, M_ * C_ / 4); }

__global__ __launch_bounds__(256) void split_v()
{ split_body(g_v, g_vh, g_vl, M_ * KH / 4); }

// ---------------------------------------------------------------------------
// transpose + split weights
// ---------------------------------------------------------------------------
__device__ __forceinline__ void tsp_body(const float* __restrict__ src,
                                         __nv_bfloat16* __restrict__ dh,
                                         __nv_bfloat16* __restrict__ dl,
                                         int R, int Cc)
{
    __shared__ float tile[32][33];
    const int c0 = blockIdx.x * 32, r0 = blockIdx.y * 32;
    const int tx = threadIdx.x, ty = threadIdx.y;
#pragma unroll
    for (int i = 0; i < 4; i++)
        tile[ty + i * 8][tx] = src[(size_t)(r0 + ty + i * 8) * Cc + c0 + tx];
    __syncthreads();
#pragma unroll
    for (int i = 0; i < 4; i++) {
        float v = tile[tx][ty + i * 8];
        __nv_bfloat16 h = __float2bfloat16(v);
        __nv_bfloat16 l = __float2bfloat16(v - __bfloat162float(h));
        size_t o = (size_t)(c0 + ty + i * 8) * R + r0 + tx;
        dh[o] = h;
        dl[o] = l;
    }
}

__global__ void tsp_q(const float* __restrict__ Wq)
{ tsp_body(Wq, g_wqt_h, g_wqt_l, C_, NH); }
__global__ void tsp_k(const float* __restrict__ Wk)
{ tsp_body(Wk, g_wkt_h, g_wkt_l, C_, KH); }
__global__ void tsp_v(const float* __restrict__ Wv)
{ tsp_body(Wv, g_wvt_h, g_wvt_l, C_, KH); }
__global__ void tsp_o(const float* __restrict__ Wout)
{ tsp_body(Wout, g_wot_h, g_wot_l, NH, C_); }

// ---------------------------------------------------------------------------
// block reduction helper
// ---------------------------------------------------------------------------
__device__ __forceinline__ float block_reduce_sum(float v)
{
    __shared__ float red[33];
#pragma unroll
    for (int d = 16; d > 0; d >>= 1) v += __shfl_xor_sync(0xffffffffu, v, d);
    int w = threadIdx.x >> 5, l = threadIdx.x & 31;
    if (l == 0) red[w] = v;
    __syncthreads();
    int nw = blockDim.x >> 5;
    if (w == 0) {
        float s = (l < nw) ? red[l] : 0.f;
#pragma unroll
        for (int d = 16; d > 0; d >>= 1) s += __shfl_xor_sync(0xffffffffu, s, d);
        if (l == 0) red[32] = s;
    }
    __syncthreads();
    return red[32];
}

#define LN_TS (9.210340371976184f / 64.f)
#define QSCALE 0.08838834764831845f

__device__ __forceinline__ void wr_hl(__nv_bfloat16* h, __nv_bfloat16* l,
                                      size_t idx, float v)
{
    __nv_bfloat16 hi = __float2bfloat16(v);
    h[idx] = hi;
    l[idx] = __float2bfloat16(v - __bfloat162float(hi));
}

// qnorm: reads fp32 g_q, writes bf16 hi/lo g_qh/g_ql (rope + scale applied)
__global__ __launch_bounds__(256) void qnorm_rope()
{
    const int row = blockIdx.x;
    const int t = row & (T_ - 1);
    const float* qr = g_q + (size_t)row * NH;

    float ss = 0.f;
#pragma unroll
    for (int it = 0; it < 2; it++) {
        int c = (threadIdx.x + it * 256) * 4;
        float4 v = *(const float4*)(qr + c);
        ss += v.x * v.x + v.y * v.y + v.z * v.z + v.w * v.w;
    }
    float tot = block_reduce_sum(ss);
    float rms = rsqrtf(tot * (1.f / NH) + 1e-6f);

#pragma unroll
    for (int it = 0; it < 4; it++) {
        int p = threadIdx.x + it * 256;
        int head = p >> 6;
        int hh = p & 63;
        int c1 = head * H_ + hh;
        int c2 = c1 + 64;
        float x1 = qr[c1] * rms;
        float x2 = qr[c2] * rms;
        float inv = expf(-(float)hh * LN_TS);
        float ang = (float)t * inv;
        float sa, ca;
        sincosf(ang, &sa, &ca);
        wr_hl(g_qh, g_ql, (size_t)row * NH + c1, (x1 * ca - x2 * sa) * QSCALE);
        wr_hl(g_qh, g_ql, (size_t)row * NH + c2, (x2 * ca + x1 * sa) * QSCALE);
    }
}

__global__ __launch_bounds__(128) void knorm_rope()
{
    const int row = blockIdx.x;
    const int t = row & (T_ - 1);
    const float* kr = g_k + (size_t)row * KH;

    int c = threadIdx.x * 4;
    float4 v = *(const float4*)(kr + c);
    float ss = v.x * v.x + v.y * v.y + v.z * v.z + v.w * v.w;
    float tot = block_reduce_sum(ss);
    float rms = rsqrtf(tot * (1.f / KH) + 1e-6f);

#pragma unroll
    for (int it = 0; it < 2; it++) {
        int p = threadIdx.x + it * 128;
        int head = p >> 6;
        int hh = p & 63;
        int c1 = head * H_ + hh;
        int c2 = c1 + 64;
        float x1 = kr[c1] * rms;
        float x2 = kr[c2] * rms;
        float inv = expf(-(float)hh * LN_TS);
        float ang = (float)t * inv;
        float sa, ca;
        sincosf(ang, &sa, &ca);
        wr_hl(g_kh, g_kl, (size_t)row * KH + c1, x1 * ca - x2 * sa);
        wr_hl(g_kh, g_kl, (size_t)row * KH + c2, x2 * ca + x1 * sa);
    }
}

// ---------------------------------------------------------------------------
// Tensor-core flash attention (bf16x3 scores + bf16x3 PV).
// grid = (T/128, NHEAD, B), 256 threads (8 warps).
// Warp w owns q-rows w*16..w*16+15 and ALL 64 keys of the tile -> warp-local
// softmax.  Direct documented-layout fragment loads (same as mgemm).
// smem word layout (uint32 units):
//   Qh[128][68] @0      Ql @8704        (K-major, stride 68 wds: banks 4r+tg)
//   Kh[64][68]  @17408  Kl @21760
//   Vth[128][36]@26112  Vtl @30720      (V transposed [h][key-pair], stride 36)
//   Ph[128][36] @35328  Pl @39936
// ---------------------------------------------------------------------------
#define QH_W 0
#define QL_W 8704
#define KH_W 17408
#define KL_W 21760
#define VH_W 26112
#define VL_W 30720
#define PH_W 35328
#define PL_W 39936
#define AT_SMEM (44544 * 4)

__global__ __launch_bounds__(256, 1) void attn_tc()
{
    extern __shared__ uint32_t s32[];
    const int tid = threadIdx.x;
    const int w = tid >> 5, lane = tid & 31;
    const int grp = lane >> 2, tg = lane & 3;
    const int b = blockIdx.z, kg = blockIdx.y, khh = kg >> 2;
    const int t0 = blockIdx.x * 128;
    const int m0 = w * 16;

    // load Q hi/lo tiles (rows t0..t0+127, head cols)
    {
        const __nv_bfloat16* qh = g_qh + (size_t)(b * T_ + t0) * NH + kg * H_;
        const __nv_bfloat16* ql = g_ql + (size_t)(b * T_ + t0) * NH + kg * H_;
        for (int i = tid; i < 128 * 16; i += 256) {
            int r = i >> 4, hc = i & 15;
            *(uint4*)&s32[QH_W + r * 68 + hc * 4] =
                *(const uint4*)(qh + (size_t)r * NH + hc * 8);
            *(uint4*)&s32[QL_W + r * 68 + hc * 4] =
                *(const uint4*)(ql + (size_t)r * NH + hc * 8);
        }
    }

    float m[2] = {-INFINITY, -INFINITY};
    float l[2] = {0.f, 0.f};
    float accO[16][4];
#pragma unroll
    for (int nt = 0; nt < 16; nt++)
#pragma unroll
        for (int r = 0; r < 4; r++) accO[nt][r] = 0.f;

    for (int s0 = 0; s0 < T_; s0 += 64) {
        __syncthreads();   // protect K/V from previous-iteration readers
        // K tiles (64 rows x 128 bf16, K-major)
        {
            const __nv_bfloat16* kh = g_kh + (size_t)(b * T_ + s0) * KH + khh * H_;
            const __nv_bfloat16* kl = g_kl + (size_t)(b * T_ + s0) * KH + khh * H_;
            for (int i = tid; i < 64 * 16; i += 256) {
                int r = i >> 4, hc = i & 15;
                *(uint4*)&s32[KH_W + r * 68 + hc * 4] =
                    *(const uint4*)(kh + (size_t)r * KH + hc * 8);
                *(uint4*)&s32[KL_W + r * 68 + hc * 4] =
                    *(const uint4*)(kl + (size_t)r * KH + hc * 8);
            }
        }
        // V transposed: Vt[h][key] as packed key-pairs.  unit: hc = 2w+i
        // (const per instruction), s2 = lane -> conflict-free stores.
#pragma unroll
        for (int i = 0; i < 2; i++) {
            int hc = 2 * w + i, s2 = lane;
            const __nv_bfloat16* vh =
                g_vh + (size_t)(b * T_ + s0 + 2 * s2) * KH + khh * H_ + hc * 8;
            const __nv_bfloat16* vl =
                g_vl + (size_t)(b * T_ + s0 + 2 * s2) * KH + khh * H_ + hc * 8;
            uint4 h0 = *(const uint4*)vh, h1 = *(const uint4*)(vh + KH);
            uint4 l0 = *(const uint4*)vl, l1 = *(const uint4*)(vl + KH);
            uint32_t wh0[4] = {h0.x, h0.y, h0.z, h0.w};
            uint32_t wh1[4] = {h1.x, h1.y, h1.z, h1.w};
            uint32_t wl0[4] = {l0.x, l0.y, l0.z, l0.w};
            uint32_t wl1[4] = {l1.x, l1.y, l1.z, l1.w};
#pragma unroll
            for (int j = 0; j < 8; j++) {
                uint32_t sh = 16 * (j & 1);
                uint32_t eh0 = (wh0[j >> 1] >> sh) & 0xFFFFu;
                uint32_t eh1 = (wh1[j >> 1] >> sh) & 0xFFFFu;
                uint32_t el0 = (wl0[j >> 1] >> sh) & 0xFFFFu;
                uint32_t el1 = (wl1[j >> 1] >> sh) & 0xFFFFu;
                s32[VH_W + (hc * 8 + j) * 36 + s2] = eh0 | (eh1 << 16);
                s32[VL_W + (hc * 8 + j) * 36 + s2] = el0 | (el1 << 16);
            }
        }
        __syncthreads();

        // ---- scores: S[16 rows][64 keys] per warp, bf16x3 ----
        float accS[8][4];
#pragma unroll
        for (int nt = 0; nt < 8; nt++)
#pragma unroll
            for (int r = 0; r < 4; r++) accS[nt][r] = 0.f;

#pragma unroll
        for (int seg = 0; seg < 3; seg++) {
            const int qw = (seg == 2) ? QL_W : QH_W;
            const int kw = (seg == 1) ? KL_W : KH_W;
#pragma unroll
            for (int ks = 0; ks < 8; ks++) {
                const int wk = ks * 8 + tg;
                int ab = qw + (m0 + grp) * 68 + wk;
                uint32_t a0 = s32[ab], a1 = s32[ab + 8 * 68];
                uint32_t a2 = s32[ab + 4], a3 = s32[ab + 8 * 68 + 4];
#pragma unroll
                for (int nt = 0; nt < 8; nt++) {
                    int bb = kw + (nt * 8 + grp) * 68 + wk;
                    MMA16816(accS[nt], a0, a1, a2, a3, s32[bb], s32[bb + 4]);
                }
            }
        }

        // ---- online softmax (warp-local; rows grp and grp+8) ----
        float mx0 = -INFINITY, mx1 = -INFINITY;
#pragma unroll
        for (int nt = 0; nt < 8; nt++) {
            mx0 = fmaxf(mx0, fmaxf(accS[nt][0], accS[nt][1]));
            mx1 = fmaxf(mx1, fmaxf(accS[nt][2], accS[nt][3]));
        }
        mx0 = fmaxf(mx0, __shfl_xor_sync(0xffffffffu, mx0, 1));
        mx0 = fmaxf(mx0, __shfl_xor_sync(0xffffffffu, mx0, 2));
        mx1 = fmaxf(mx1, __shfl_xor_sync(0xffffffffu, mx1, 1));
        mx1 = fmaxf(mx1, __shfl_xor_sync(0xffffffffu, mx1, 2));
        float mn0 = fmaxf(m[0], mx0), mn1 = fmaxf(m[1], mx1);
        float c0 = expf(m[0] - mn0), c1 = expf(m[1] - mn1);
        m[0] = mn0;
        m[1] = mn1;

        float rs0 = 0.f, rs1 = 0.f;
#pragma unroll
        for (int nt = 0; nt < 8; nt++) {
            float p0 = __expf(accS[nt][0] - mn0);
            float p1 = __expf(accS[nt][1] - mn0);
            float p2 = __expf(accS[nt][2] - mn1);
            float p3 = __expf(accS[nt][3] - mn1);
            rs0 += p0 + p1;
            rs1 += p2 + p3;
            // pack bf16 hi/lo pairs, store at word (nt*4+tg) of the rows
            __nv_bfloat16 h0 = __float2bfloat16(p0), h1 = __float2bfloat16(p1);
            __nv_bfloat16 h2 = __float2bfloat16(p2), h3 = __float2bfloat16(p3);
            float q0 = p0 - __bfloat162float(h0), q1 = p1 - __bfloat162float(h1);
            float q2 = p2 - __bfloat162float(h2), q3 = p3 - __bfloat162float(h3);
            uint32_t ph01 = ((uint32_t)__bfloat16_as_ushort(h0)) |
                            ((uint32_t)__bfloat16_as_ushort(h1) << 16);
            uint32_t ph23 = ((uint32_t)__bfloat16_as_ushort(h2)) |
                            ((uint32_t)__bfloat16_as_ushort(h3) << 16);
            uint32_t pl01 = ((uint32_t)__bfloat16_as_ushort(__float2bfloat16(q0))) |
                            ((uint32_t)__bfloat16_as_ushort(__float2bfloat16(q1)) << 16);
            uint32_t pl23 = ((uint32_t)__bfloat16_as_ushort(__float2bfloat16(q2))) |
                            ((uint32_t)__bfloat16_as_ushort(__float2bfloat16(q3)) << 16);
            s32[PH_W + (m0 + grp) * 36 + nt * 4 + tg] = ph01;
            s32[PH_W + (m0 + grp + 8) * 36 + nt * 4 + tg] = ph23;
            s32[PL_W + (m0 + grp) * 36 + nt * 4 + tg] = pl01;
            s32[PL_W + (m0 + grp + 8) * 36 + nt * 4 + tg] = pl23;
        }
        rs0 += __shfl_xor_sync(0xffffffffu, rs0, 1);
        rs0 += __shfl_xor_sync(0xffffffffu, rs0, 2);
        rs1 += __shfl_xor_sync(0xffffffffu, rs1, 1);
        rs1 += __shfl_xor_sync(0xffffffffu, rs1, 2);
        l[0] = l[0] * c0 + rs0;
        l[1] = l[1] * c1 + rs1;
#pragma unroll
        for (int nt = 0; nt < 16; nt++) {
            accO[nt][0] *= c0;
            accO[nt][1] *= c0;
            accO[nt][2] *= c1;
            accO[nt][3] *= c1;
        }
        __syncwarp();   // P visible within warp

        // ---- PV: O[16][128] += P[16][64] * V[64][128], bf16x3 ----
#pragma unroll
        for (int seg = 0; seg < 3; seg++) {
            const int aw = (seg == 2) ? PL_W : PH_W;
            const int bw = (seg == 1) ? VL_W : VH_W;
#pragma unroll
            for (int ks = 0; ks < 4; ks++) {
                const int wk = ks * 8 + tg;
                int ab = aw + (m0 + grp) * 36 + wk;
                uint32_t a0 = s32[ab], a1 = s32[ab + 8 * 36];
                uint32_t a2 = s32[ab + 4], a3 = s32[ab + 8 * 36 + 4];
#pragma unroll
                for (int nt = 0; nt < 16; nt++) {
                    int bb = bw + (nt * 8 + grp) * 36 + wk;
                    MMA16816(accO[nt], a0, a1, a2, a3, s32[bb], s32[bb + 4]);
                }
            }
        }
    }

    // epilogue: write g_ech/g_ecl bf16 hi/lo directly
    float inv0 = 1.f / l[0], inv1 = 1.f / l[1];
    size_t r0 = (size_t)(b * T_ + t0 + m0 + grp) * NH + kg * H_;
    size_t r1 = (size_t)(b * T_ + t0 + m0 + grp + 8) * NH + kg * H_;
#pragma unroll
    for (int nt = 0; nt < 16; nt++) {
        int col = nt * 8 + tg * 2;
        float o0 = accO[nt][0] * inv0, o1 = accO[nt][1] * inv0;
        float o2 = accO[nt][2] * inv1, o3 = accO[nt][3] * inv1;
        __nv_bfloat16 h0 = __float2bfloat16(o0), h1 = __float2bfloat16(o1);
        __nv_bfloat16 h2 = __float2bfloat16(o2), h3 = __float2bfloat16(o3);
        *(__nv_bfloat162*)(g_ech + r0 + col) = __nv_bfloat162(h0, h1);
        *(__nv_bfloat162*)(g_ech + r1 + col) = __nv_bfloat162(h2, h3);
        *(__nv_bfloat162*)(g_ecl + r0 + col) = __nv_bfloat162(
            __float2bfloat16(o0 - __bfloat162float(h0)),
            __float2bfloat16(o1 - __bfloat162float(h1)));
        *(__nv_bfloat162*)(g_ecl + r1 + col) = __nv_bfloat162(
            __float2bfloat16(o2 - __bfloat162float(h2)),
            __float2bfloat16(o3 - __bfloat162float(h3)));
    }
}

// ---------------------------------------------------------------------------
extern "C" void kernel_launch(void* const* d_in, const int* in_sizes, int n_in,
                              void* d_out, int out_size)
{
    const float* x    = (const float*)d_in[0];
    const float* Wq   = (const float*)d_in[1];
    const float* Wk   = (const float*)d_in[2];
    const float* Wv   = (const float*)d_in[3];
    const float* Wout = (const float*)d_in[4];
    float* out = (float*)d_out;

    (void)cudaFuncSetAttribute(attn_tc,
                               cudaFuncAttributeMaxDynamicSharedMemorySize, AT_SMEM);
    (void)cudaFuncSetAttribute(mgemm_q,
                               cudaFuncAttributeMaxDynamicSharedMemorySize, MG_SMEM);
    (void)cudaFuncSetAttribute(mgemm_k,
                               cudaFuncAttributeMaxDynamicSharedMemorySize, MG_SMEM);
    (void)cudaFuncSetAttribute(mgemm_v,
                               cudaFuncAttributeMaxDynamicSharedMemorySize, MG_SMEM);
    (void)cudaFuncSetAttribute(mgemm_o,
                               cudaFuncAttributeMaxDynamicSharedMemorySize, MG_SMEM);

    // split x into bf16 hi/lo
    split_x<<<M_ * C_ / 4 / 256, 256>>>(x);

    // transpose + split weights
    tsp_q<<<dim3(NH / 32, C_ / 32), dim3(32, 8)>>>(Wq);
    tsp_k<<<dim3(KH / 32, C_ / 32), dim3(32, 8)>>>(Wk);
    tsp_v<<<dim3(KH / 32, C_ / 32), dim3(32, 8)>>>(Wv);
    tsp_o<<<dim3(C_ / 32, NH / 32), dim3(32, 8)>>>(Wout);

    // projections (tensor cores)
    mgemm_q<<<dim3(NH / 128, M_ / 128), 256, MG_SMEM>>>();
    mgemm_k<<<dim3(KH / 128, M_ / 128), 256, MG_SMEM>>>();
    mgemm_v<<<dim3(KH / 128, M_ / 128), 256, MG_SMEM>>>();

    // norms + rope -> bf16 hi/lo; v split
    qnorm_rope<<<M_, 256>>>();
    knorm_rope<<<M_, 128>>>();
    split_v<<<M_ * KH / 4 / 256, 256>>>();

    // attention (tensor cores, writes g_ech/g_ecl directly)
    attn_tc<<<dim3(T_ / 128, NHEAD, B_), 256, AT_SMEM>>>();

    // out projection
    mgemm_o<<<dim3(C_ / 128, M_ / 128), 256, MG_SMEM>>>(out);
}

// round 15
// speedup vs baseline: 2.6107x; 1.0663x over previous
#include <cuda_runtime.h>
#include <cuda_bf16.h>
#include <math.h>
#include <stdint.h>

// Problem constants
#define B_   4
#define T_   2048
#define C_   2048
#define NHEAD 16
#define KHEAD 4
#define H_   128
#define NH   2048   // NHEAD*H
#define KH   512    // KHEAD*H
#define M_   8192   // B*T
#define KTOT 2048   // K dim of every projection GEMM

// fp32 scratch (device globals; referenced ONLY from device code)
__device__ float g_q[(size_t)M_ * NH];
__device__ float g_k[(size_t)M_ * KH];
__device__ float g_v[(size_t)M_ * KH];

// bf16 hi/lo split scratch
__device__ __nv_bfloat16 g_xh[(size_t)M_ * C_], g_xl[(size_t)M_ * C_];
__device__ __nv_bfloat16 g_wqt_h[(size_t)NH * C_], g_wqt_l[(size_t)NH * C_];
__device__ __nv_bfloat16 g_wkt_h[(size_t)KH * C_], g_wkt_l[(size_t)KH * C_];
__device__ __nv_bfloat16 g_wvt_h[(size_t)KH * C_], g_wvt_l[(size_t)KH * C_];
__device__ __nv_bfloat16 g_wot_h[(size_t)C_ * NH], g_wot_l[(size_t)C_ * NH];
__device__ __nv_bfloat16 g_ech[(size_t)M_ * NH], g_ecl[(size_t)M_ * NH];
__device__ __nv_bfloat16 g_qh[(size_t)M_ * NH], g_ql[(size_t)M_ * NH];
__device__ __nv_bfloat16 g_kh[(size_t)M_ * KH], g_kl[(size_t)M_ * KH];
__device__ __nv_bfloat16 g_vh[(size_t)M_ * KH], g_vl[(size_t)M_ * KH];

// ---------------------------------------------------------------------------
// helpers
// ---------------------------------------------------------------------------
__device__ __forceinline__ uint32_t smem_u32(const void* p)
{
    uint32_t a;
    asm("{ .reg .u64 t; cvta.to.shared.u64 t, %1; cvt.u32.u64 %0, t; }"
        : "=r"(a) : "l"(p));
    return a;
}

__device__ __forceinline__ void cp16(uint32_t dst, const void* src)
{
    asm volatile("cp.async.cg.shared.global [%0], [%1], 16;"
                 :: "r"(dst), "l"(src) : "memory");
}

#define MMA16816(acc, a0, a1, a2, a3, b0, b1)                                  \
    asm volatile(                                                              \
        "mma.sync.aligned.m16n8k16.row.col.f32.bf16.bf16.f32 "                 \
        "{%0,%1,%2,%3}, {%4,%5,%6,%7}, {%8,%9}, {%0,%1,%2,%3};"                \
        : "+f"((acc)[0]), "+f"((acc)[1]), "+f"((acc)[2]), "+f"((acc)[3])       \
        : "r"(a0), "r"(a1), "r"(a2), "r"(a3), "r"(b0), "r"(b1))

// ---------------------------------------------------------------------------
// bf16x3 GEMM, fused segments: per 32-K chunk load Ah,Al,Bh,Bl once and do
// aH*bH + aH*bL + aL*bH.  64 chunks, 3 stages x 40KB, prefetch distance 2.
// CTA 128x128, 8 warps (warp tile 64x32).  Direct fragment loads.
// smem stage layout (words): AH @0, AL @2560, BH @5120, BL @7680
// ---------------------------------------------------------------------------
#define NCHUNK   64
#define ROWW32   20                    // padded row width (40 bf16) in words
#define TILE_W   2560                  // words per 128x40 tile
#define STG_W    10240                 // words per stage (4 tiles)
#define STG_B    40960                 // bytes per stage
#define MG_SMEM  (3 * STG_B)           // 122880

__device__ __forceinline__ void mgemm_body(const __nv_bfloat16* __restrict__ Ah,
                                           const __nv_bfloat16* __restrict__ Al,
                                           const __nv_bfloat16* __restrict__ Bh,
                                           const __nv_bfloat16* __restrict__ Bl,
                                           float* __restrict__ C, int Ntot)
{
    extern __shared__ char smx[];
    const uint32_t sb = smem_u32(smx);
    const uint32_t* s32 = (const uint32_t*)smx;
    const int tid = threadIdx.x;
    const int bm = blockIdx.y * 128, bn = blockIdx.x * 128;
    const int w = tid >> 5, lane = tid & 31;
    const int m0 = (w >> 2) * 64, n0 = (w & 3) * 32;
    const int grp = lane >> 2, tg = lane & 3;

    float acc[4][4][4];
#pragma unroll
    for (int mt = 0; mt < 4; mt++)
#pragma unroll
        for (int nt = 0; nt < 4; nt++)
#pragma unroll
            for (int r = 0; r < 4; r++) acc[mt][nt][r] = 0.f;

    auto load_stage = [&](int c) {
        const int kk = c << 5;
        const uint32_t base = sb + (c % 3) * STG_B;
#pragma unroll
        for (int i = 0; i < 2; i++) {
            int u = tid + (i << 8);
            int row = u >> 2, k16 = u & 3;
            uint32_t so = (uint32_t)(row * 80 + k16 * 16);
            size_t ga = (size_t)(bm + row) * KTOT + kk + k16 * 8;
            size_t gb = (size_t)(bn + row) * KTOT + kk + k16 * 8;
            cp16(base + so, Ah + ga);
            cp16(base + TILE_W * 4 + so, Al + ga);
            cp16(base + TILE_W * 8 + so, Bh + gb);
            cp16(base + TILE_W * 12 + so, Bl + gb);
        }
        asm volatile("cp.async.commit_group;" ::: "memory");
    };

    load_stage(0);
    load_stage(1);

    for (int c = 0; c < NCHUNK; c++) {
        asm volatile("cp.async.wait_group 1;" ::: "memory");   // chunk c landed
        __syncthreads();
        if (c + 2 < NCHUNK) load_stage(c + 2);
        else asm volatile("cp.async.commit_group;" ::: "memory");

        const int wstg = (c % 3) * STG_W;
#pragma unroll
        for (int ks = 0; ks < 2; ks++) {
            const int wk = ks * 8 + tg;
            uint32_t aF[4][4], bH[4][2], bL[4][2];
            // aH fragments
#pragma unroll
            for (int mt = 0; mt < 4; mt++) {
                int base = wstg + (m0 + mt * 16 + grp) * ROWW32 + wk;
                aF[mt][0] = s32[base];
                aF[mt][1] = s32[base + 8 * ROWW32];
                aF[mt][2] = s32[base + 4];
                aF[mt][3] = s32[base + 8 * ROWW32 + 4];
            }
            // bH + bL fragments
#pragma unroll
            for (int nt = 0; nt < 4; nt++) {
                int bh = wstg + TILE_W * 2 + (n0 + nt * 8 + grp) * ROWW32 + wk;
                int bl = wstg + TILE_W * 3 + (n0 + nt * 8 + grp) * ROWW32 + wk;
                bH[nt][0] = s32[bh];
                bH[nt][1] = s32[bh + 4];
                bL[nt][0] = s32[bl];
                bL[nt][1] = s32[bl + 4];
            }
            // aH*bH and aH*bL
#pragma unroll
            for (int mt = 0; mt < 4; mt++)
#pragma unroll
                for (int nt = 0; nt < 4; nt++) {
                    MMA16816(acc[mt][nt], aF[mt][0], aF[mt][1], aF[mt][2],
                             aF[mt][3], bH[nt][0], bH[nt][1]);
                    MMA16816(acc[mt][nt], aF[mt][0], aF[mt][1], aF[mt][2],
                             aF[mt][3], bL[nt][0], bL[nt][1]);
                }
            // aL fragments, aL*bH
#pragma unroll
            for (int mt = 0; mt < 4; mt++) {
                int base = wstg + TILE_W + (m0 + mt * 16 + grp) * ROWW32 + wk;
                aF[mt][0] = s32[base];
                aF[mt][1] = s32[base + 8 * ROWW32];
                aF[mt][2] = s32[base + 4];
                aF[mt][3] = s32[base + 8 * ROWW32 + 4];
            }
#pragma unroll
            for (int mt = 0; mt < 4; mt++)
#pragma unroll
                for (int nt = 0; nt < 4; nt++)
                    MMA16816(acc[mt][nt], aF[mt][0], aF[mt][1], aF[mt][2],
                             aF[mt][3], bH[nt][0], bH[nt][1]);
        }
    }

#pragma unroll
    for (int mt = 0; mt < 4; mt++)
#pragma unroll
        for (int nt = 0; nt < 4; nt++) {
            float* cp0 = C + (size_t)(bm + m0 + mt * 16 + grp) * Ntot
                           + bn + n0 + nt * 8 + tg * 2;
            *(float2*)cp0 = make_float2(acc[mt][nt][0], acc[mt][nt][1]);
            *(float2*)(cp0 + (size_t)8 * Ntot) =
                make_float2(acc[mt][nt][2], acc[mt][nt][3]);
        }
}

__global__ __launch_bounds__(256) void mgemm_q()
{ mgemm_body(g_xh, g_xl, g_wqt_h, g_wqt_l, g_q, NH); }
__global__ __launch_bounds__(256) void mgemm_k()
{ mgemm_body(g_xh, g_xl, g_wkt_h, g_wkt_l, g_k, KH); }
__global__ __launch_bounds__(256) void mgemm_v()
{ mgemm_body(g_xh, g_xl, g_wvt_h, g_wvt_l, g_v, KH); }
__global__ __launch_bounds__(256) void mgemm_o(float* __restrict__ out)
{ mgemm_body(g_ech, g_ecl, g_wot_h, g_wot_l, out, C_); }

// ---------------------------------------------------------------------------
// fp32 -> bf16 hi/lo split
// ---------------------------------------------------------------------------
__device__ __forceinline__ void split_body(const float* __restrict__ s,
                                           __nv_bfloat16* __restrict__ h,
                                           __nv_bfloat16* __restrict__ l,
                                           int n4)
{
    int i = blockIdx.x * 256 + threadIdx.x;
    if (i >= n4) return;
    float4 v = ((const float4*)s)[i];
    __nv_bfloat16 h0 = __float2bfloat16(v.x), h1 = __float2bfloat16(v.y);
    __nv_bfloat16 h2 = __float2bfloat16(v.z), h3 = __float2bfloat16(v.w);
    __nv_bfloat16 l0 = __float2bfloat16(v.x - __bfloat162float(h0));
    __nv_bfloat16 l1 = __float2bfloat16(v.y - __bfloat162float(h1));
    __nv_bfloat16 l2 = __float2bfloat16(v.z - __bfloat162float(h2));
    __nv_bfloat16 l3 = __float2bfloat16(v.w - __bfloat162float(h3));
    ((__nv_bfloat162*)h)[2 * i]     = __nv_bfloat162(h0, h1);
    ((__nv_bfloat162*)h)[2 * i + 1] = __nv_bfloat162(h2, h3);
    ((__nv_bfloat162*)l)[2 * i]     = __nv_bfloat162(l0, l1);
    ((__nv_bfloat162*)l)[2 * i + 1] = __nv_bfloat162(l2, l3);
}

__global__ __launch_bounds__(256) void split_x(const float* __restrict__ x)
{ split_body(x, g_xh, g_xl, M_ * C_ / 4); }

__global__ __launch_bounds__(256) void split_v()
{ split_body(g_v, g_vh, g_vl, M_ * KH / 4); }

// ---------------------------------------------------------------------------
// transpose + split weights
// ---------------------------------------------------------------------------
__device__ __forceinline__ void tsp_body(const float* __restrict__ src,
                                         __nv_bfloat16* __restrict__ dh,
                                         __nv_bfloat16* __restrict__ dl,
                                         int R, int Cc)
{
    __shared__ float tile[32][33];
    const int c0 = blockIdx.x * 32, r0 = blockIdx.y * 32;
    const int tx = threadIdx.x, ty = threadIdx.y;
#pragma unroll
    for (int i = 0; i < 4; i++)
        tile[ty + i * 8][tx] = src[(size_t)(r0 + ty + i * 8) * Cc + c0 + tx];
    __syncthreads();
#pragma unroll
    for (int i = 0; i < 4; i++) {
        float v = tile[tx][ty + i * 8];
        __nv_bfloat16 h = __float2bfloat16(v);
        __nv_bfloat16 l = __float2bfloat16(v - __bfloat162float(h));
        size_t o = (size_t)(c0 + ty + i * 8) * R + r0 + tx;
        dh[o] = h;
        dl[o] = l;
    }
}

__global__ void tsp_q(const float* __restrict__ Wq)
{ tsp_body(Wq, g_wqt_h, g_wqt_l, C_, NH); }
__global__ void tsp_k(const float* __restrict__ Wk)
{ tsp_body(Wk, g_wkt_h, g_wkt_l, C_, KH); }
__global__ void tsp_v(const float* __restrict__ Wv)
{ tsp_body(Wv, g_wvt_h, g_wvt_l, C_, KH); }
__global__ void tsp_o(const float* __restrict__ Wout)
{ tsp_body(Wout, g_wot_h, g_wot_l, NH, C_); }

// ---------------------------------------------------------------------------
// block reduction helper
// ---------------------------------------------------------------------------
__device__ __forceinline__ float block_reduce_sum(float v)
{
    __shared__ float red[33];
#pragma unroll
    for (int d = 16; d > 0; d >>= 1) v += __shfl_xor_sync(0xffffffffu, v, d);
    int w = threadIdx.x >> 5, l = threadIdx.x & 31;
    if (l == 0) red[w] = v;
    __syncthreads();
    int nw = blockDim.x >> 5;
    if (w == 0) {
        float s = (l < nw) ? red[l] : 0.f;
#pragma unroll
        for (int d = 16; d > 0; d >>= 1) s += __shfl_xor_sync(0xffffffffu, s, d);
        if (l == 0) red[32] = s;
    }
    __syncthreads();
    return red[32];
}

#define LN_TS (9.210340371976184f / 64.f)
#define QSCALE 0.08838834764831845f

__device__ __forceinline__ void wr_hl(__nv_bfloat16* h, __nv_bfloat16* l,
                                      size_t idx, float v)
{
    __nv_bfloat16 hi = __float2bfloat16(v);
    h[idx] = hi;
    l[idx] = __float2bfloat16(v - __bfloat162float(hi));
}

__global__ __launch_bounds__(256) void qnorm_rope()
{
    const int row = blockIdx.x;
    const int t = row & (T_ - 1);
    const float* qr = g_q + (size_t)row * NH;

    float ss = 0.f;
#pragma unroll
    for (int it = 0; it < 2; it++) {
        int c = (threadIdx.x + it * 256) * 4;
        float4 v = *(const float4*)(qr + c);
        ss += v.x * v.x + v.y * v.y + v.z * v.z + v.w * v.w;
    }
    float tot = block_reduce_sum(ss);
    float rms = rsqrtf(tot * (1.f / NH) + 1e-6f);

#pragma unroll
    for (int it = 0; it < 4; it++) {
        int p = threadIdx.x + it * 256;
        int head = p >> 6;
        int hh = p & 63;
        int c1 = head * H_ + hh;
        int c2 = c1 + 64;
        float x1 = qr[c1] * rms;
        float x2 = qr[c2] * rms;
        float inv = expf(-(float)hh * LN_TS);
        float ang = (float)t * inv;
        float sa, ca;
        sincosf(ang, &sa, &ca);
        wr_hl(g_qh, g_ql, (size_t)row * NH + c1, (x1 * ca - x2 * sa) * QSCALE);
        wr_hl(g_qh, g_ql, (size_t)row * NH + c2, (x2 * ca + x1 * sa) * QSCALE);
    }
}

__global__ __launch_bounds__(128) void knorm_rope()
{
    const int row = blockIdx.x;
    const int t = row & (T_ - 1);
    const float* kr = g_k + (size_t)row * KH;

    int c = threadIdx.x * 4;
    float4 v = *(const float4*)(kr + c);
    float ss = v.x * v.x + v.y * v.y + v.z * v.z + v.w * v.w;
    float tot = block_reduce_sum(ss);
    float rms = rsqrtf(tot * (1.f / KH) + 1e-6f);

#pragma unroll
    for (int it = 0; it < 2; it++) {
        int p = threadIdx.x + it * 128;
        int head = p >> 6;
        int hh = p & 63;
        int c1 = head * H_ + hh;
        int c2 = c1 + 64;
        float x1 = kr[c1] * rms;
        float x2 = kr[c2] * rms;
        float inv = expf(-(float)hh * LN_TS);
        float ang = (float)t * inv;
        float sa, ca;
        sincosf(ang, &sa, &ca);
        wr_hl(g_kh, g_kl, (size_t)row * KH + c1, x1 * ca - x2 * sa);
        wr_hl(g_kh, g_kl, (size_t)row * KH + c2, x2 * ca + x1 * sa);
    }
}

// ---------------------------------------------------------------------------
// Tensor-core flash attention (bf16x3 scores + bf16x3 PV).  (proven in R11)
// ---------------------------------------------------------------------------
#define QH_W 0
#define QL_W 8704
#define KH_W 17408
#define KL_W 21760
#define VH_W 26112
#define VL_W 30720
#define PH_W 35328
#define PL_W 39936
#define AT_SMEM (44544 * 4)

__global__ __launch_bounds__(256, 1) void attn_tc()
{
    extern __shared__ uint32_t s32[];
    const int tid = threadIdx.x;
    const int w = tid >> 5, lane = tid & 31;
    const int grp = lane >> 2, tg = lane & 3;
    const int b = blockIdx.z, kg = blockIdx.y, khh = kg >> 2;
    const int t0 = blockIdx.x * 128;
    const int m0 = w * 16;

    {
        const __nv_bfloat16* qh = g_qh + (size_t)(b * T_ + t0) * NH + kg * H_;
        const __nv_bfloat16* ql = g_ql + (size_t)(b * T_ + t0) * NH + kg * H_;
        for (int i = tid; i < 128 * 16; i += 256) {
            int r = i >> 4, hc = i & 15;
            *(uint4*)&s32[QH_W + r * 68 + hc * 4] =
                *(const uint4*)(qh + (size_t)r * NH + hc * 8);
            *(uint4*)&s32[QL_W + r * 68 + hc * 4] =
                *(const uint4*)(ql + (size_t)r * NH + hc * 8);
        }
    }

    float m[2] = {-INFINITY, -INFINITY};
    float l[2] = {0.f, 0.f};
    float accO[16][4];
#pragma unroll
    for (int nt = 0; nt < 16; nt++)
#pragma unroll
        for (int r = 0; r < 4; r++) accO[nt][r] = 0.f;

    for (int s0 = 0; s0 < T_; s0 += 64) {
        __syncthreads();
        {
            const __nv_bfloat16* kh = g_kh + (size_t)(b * T_ + s0) * KH + khh * H_;
            const __nv_bfloat16* kl = g_kl + (size_t)(b * T_ + s0) * KH + khh * H_;
            for (int i = tid; i < 64 * 16; i += 256) {
                int r = i >> 4, hc = i & 15;
                *(uint4*)&s32[KH_W + r * 68 + hc * 4] =
                    *(const uint4*)(kh + (size_t)r * KH + hc * 8);
                *(uint4*)&s32[KL_W + r * 68 + hc * 4] =
                    *(const uint4*)(kl + (size_t)r * KH + hc * 8);
            }
        }
#pragma unroll
        for (int i = 0; i < 2; i++) {
            int hc = 2 * w + i, s2 = lane;
            const __nv_bfloat16* vh =
                g_vh + (size_t)(b * T_ + s0 + 2 * s2) * KH + khh * H_ + hc * 8;
            const __nv_bfloat16* vl =
                g_vl + (size_t)(b * T_ + s0 + 2 * s2) * KH + khh * H_ + hc * 8;
            uint4 h0 = *(const uint4*)vh, h1 = *(const uint4*)(vh + KH);
            uint4 l0 = *(const uint4*)vl, l1 = *(const uint4*)(vl + KH);
            uint32_t wh0[4] = {h0.x, h0.y, h0.z, h0.w};
            uint32_t wh1[4] = {h1.x, h1.y, h1.z, h1.w};
            uint32_t wl0[4] = {l0.x, l0.y, l0.z, l0.w};
            uint32_t wl1[4] = {l1.x, l1.y, l1.z, l1.w};
#pragma unroll
            for (int j = 0; j < 8; j++) {
                uint32_t sh = 16 * (j & 1);
                uint32_t eh0 = (wh0[j >> 1] >> sh) & 0xFFFFu;
                uint32_t eh1 = (wh1[j >> 1] >> sh) & 0xFFFFu;
                uint32_t el0 = (wl0[j >> 1] >> sh) & 0xFFFFu;
                uint32_t el1 = (wl1[j >> 1] >> sh) & 0xFFFFu;
                s32[VH_W + (hc * 8 + j) * 36 + s2] = eh0 | (eh1 << 16);
                s32[VL_W + (hc * 8 + j) * 36 + s2] = el0 | (el1 << 16);
            }
        }
        __syncthreads();

        float accS[8][4];
#pragma unroll
        for (int nt = 0; nt < 8; nt++)
#pragma unroll
            for (int r = 0; r < 4; r++) accS[nt][r] = 0.f;

#pragma unroll
        for (int seg = 0; seg < 3; seg++) {
            const int qw = (seg == 2) ? QL_W : QH_W;
            const int kw = (seg == 1) ? KL_W : KH_W;
#pragma unroll
            for (int ks = 0; ks < 8; ks++) {
                const int wk = ks * 8 + tg;
                int ab = qw + (m0 + grp) * 68 + wk;
                uint32_t a0 = s32[ab], a1 = s32[ab + 8 * 68];
                uint32_t a2 = s32[ab + 4], a3 = s32[ab + 8 * 68 + 4];
#pragma unroll
                for (int nt = 0; nt < 8; nt++) {
                    int bb = kw + (nt * 8 + grp) * 68 + wk;
                    MMA16816(accS[nt], a0, a1, a2, a3, s32[bb], s32[bb + 4]);
                }
            }
        }

        float mx0 = -INFINITY, mx1 = -INFINITY;
#pragma unroll
        for (int nt = 0; nt < 8; nt++) {
            mx0 = fmaxf(mx0, fmaxf(accS[nt][0], accS[nt][1]));
            mx1 = fmaxf(mx1, fmaxf(accS[nt][2], accS[nt][3]));
        }
        mx0 = fmaxf(mx0, __shfl_xor_sync(0xffffffffu, mx0, 1));
        mx0 = fmaxf(mx0, __shfl_xor_sync(0xffffffffu, mx0, 2));
        mx1 = fmaxf(mx1, __shfl_xor_sync(0xffffffffu, mx1, 1));
        mx1 = fmaxf(mx1, __shfl_xor_sync(0xffffffffu, mx1, 2));
        float mn0 = fmaxf(m[0], mx0), mn1 = fmaxf(m[1], mx1);
        float c0 = expf(m[0] - mn0), c1 = expf(m[1] - mn1);
        m[0] = mn0;
        m[1] = mn1;

        float rs0 = 0.f, rs1 = 0.f;
#pragma unroll
        for (int nt = 0; nt < 8; nt++) {
            float p0 = __expf(accS[nt][0] - mn0);
            float p1 = __expf(accS[nt][1] - mn0);
            float p2 = __expf(accS[nt][2] - mn1);
            float p3 = __expf(accS[nt][3] - mn1);
            rs0 += p0 + p1;
            rs1 += p2 + p3;
            __nv_bfloat16 h0 = __float2bfloat16(p0), h1 = __float2bfloat16(p1);
            __nv_bfloat16 h2 = __float2bfloat16(p2), h3 = __float2bfloat16(p3);
            float q0 = p0 - __bfloat162float(h0), q1 = p1 - __bfloat162float(h1);
            float q2 = p2 - __bfloat162float(h2), q3 = p3 - __bfloat162float(h3);
            uint32_t ph01 = ((uint32_t)__bfloat16_as_ushort(h0)) |
                            ((uint32_t)__bfloat16_as_ushort(h1) << 16);
            uint32_t ph23 = ((uint32_t)__bfloat16_as_ushort(h2)) |
                            ((uint32_t)__bfloat16_as_ushort(h3) << 16);
            uint32_t pl01 = ((uint32_t)__bfloat16_as_ushort(__float2bfloat16(q0))) |
                            ((uint32_t)__bfloat16_as_ushort(__float2bfloat16(q1)) << 16);
            uint32_t pl23 = ((uint32_t)__bfloat16_as_ushort(__float2bfloat16(q2))) |
                            ((uint32_t)__bfloat16_as_ushort(__float2bfloat16(q3)) << 16);
            s32[PH_W + (m0 + grp) * 36 + nt * 4 + tg] = ph01;
            s32[PH_W + (m0 + grp + 8) * 36 + nt * 4 + tg] = ph23;
            s32[PL_W + (m0 + grp) * 36 + nt * 4 + tg] = pl01;
            s32[PL_W + (m0 + grp + 8) * 36 + nt * 4 + tg] = pl23;
        }
        rs0 += __shfl_xor_sync(0xffffffffu, rs0, 1);
        rs0 += __shfl_xor_sync(0xffffffffu, rs0, 2);
        rs1 += __shfl_xor_sync(0xffffffffu, rs1, 1);
        rs1 += __shfl_xor_sync(0xffffffffu, rs1, 2);
        l[0] = l[0] * c0 + rs0;
        l[1] = l[1] * c1 + rs1;
#pragma unroll
        for (int nt = 0; nt < 16; nt++) {
            accO[nt][0] *= c0;
            accO[nt][1] *= c0;
            accO[nt][2] *= c1;
            accO[nt][3] *= c1;
        }
        __syncwarp();

#pragma unroll
        for (int seg = 0; seg < 3; seg++) {
            const int aw = (seg == 2) ? PL_W : PH_W;
            const int bw = (seg == 1) ? VL_W : VH_W;
#pragma unroll
            for (int ks = 0; ks < 4; ks++) {
                const int wk = ks * 8 + tg;
                int ab = aw + (m0 + grp) * 36 + wk;
                uint32_t a0 = s32[ab], a1 = s32[ab + 8 * 36];
                uint32_t a2 = s32[ab + 4], a3 = s32[ab + 8 * 36 + 4];
#pragma unroll
                for (int nt = 0; nt < 16; nt++) {
                    int bb = bw + (nt * 8 + grp) * 36 + wk;
                    MMA16816(accO[nt], a0, a1, a2, a3, s32[bb], s32[bb + 4]);
                }
            }
        }
    }

    float inv0 = 1.f / l[0], inv1 = 1.f / l[1];
    size_t r0 = (size_t)(b * T_ + t0 + m0 + grp) * NH + kg * H_;
    size_t r1 = (size_t)(b * T_ + t0 + m0 + grp + 8) * NH + kg * H_;
#pragma unroll
    for (int nt = 0; nt < 16; nt++) {
        int col = nt * 8 + tg * 2;
        float o0 = accO[nt][0] * inv0, o1 = accO[nt][1] * inv0;
        float o2 = accO[nt][2] * inv1, o3 = accO[nt][3] * inv1;
        __nv_bfloat16 h0 = __float2bfloat16(o0), h1 = __float2bfloat16(o1);
        __nv_bfloat16 h2 = __float2bfloat16(o2), h3 = __float2bfloat16(o3);
        *(__nv_bfloat162*)(g_ech + r0 + col) = __nv_bfloat162(h0, h1);
        *(__nv_bfloat162*)(g_ech + r1 + col) = __nv_bfloat162(h2, h3);
        *(__nv_bfloat162*)(g_ecl + r0 + col) = __nv_bfloat162(
            __float2bfloat16(o0 - __bfloat162float(h0)),
            __float2bfloat16(o1 - __bfloat162float(h1)));
        *(__nv_bfloat162*)(g_ecl + r1 + col) = __nv_bfloat162(
            __float2bfloat16(o2 - __bfloat162float(h2)),
            __float2bfloat16(o3 - __bfloat162float(h3)));
    }
}

// ---------------------------------------------------------------------------
extern "C" void kernel_launch(void* const* d_in, const int* in_sizes, int n_in,
                              void* d_out, int out_size)
{
    const float* x    = (const float*)d_in[0];
    const float* Wq   = (const float*)d_in[1];
    const float* Wk   = (const float*)d_in[2];
    const float* Wv   = (const float*)d_in[3];
    const float* Wout = (const float*)d_in[4];
    float* out = (float*)d_out;

    (void)cudaFuncSetAttribute(attn_tc,
                               cudaFuncAttributeMaxDynamicSharedMemorySize, AT_SMEM);
    (void)cudaFuncSetAttribute(mgemm_q,
                               cudaFuncAttributeMaxDynamicSharedMemorySize, MG_SMEM);
    (void)cudaFuncSetAttribute(mgemm_k,
                               cudaFuncAttributeMaxDynamicSharedMemorySize, MG_SMEM);
    (void)cudaFuncSetAttribute(mgemm_v,
                               cudaFuncAttributeMaxDynamicSharedMemorySize, MG_SMEM);
    (void)cudaFuncSetAttribute(mgemm_o,
                               cudaFuncAttributeMaxDynamicSharedMemorySize, MG_SMEM);

    split_x<<<M_ * C_ / 4 / 256, 256>>>(x);

    tsp_q<<<dim3(NH / 32, C_ / 32), dim3(32, 8)>>>(Wq);
    tsp_k<<<dim3(KH / 32, C_ / 32), dim3(32, 8)>>>(Wk);
    tsp_v<<<dim3(KH / 32, C_ / 32), dim3(32, 8)>>>(Wv);
    tsp_o<<<dim3(C_ / 32, NH / 32), dim3(32, 8)>>>(Wout);

    mgemm_q<<<dim3(NH / 128, M_ / 128), 256, MG_SMEM>>>();
    mgemm_k<<<dim3(KH / 128, M_ / 128), 256, MG_SMEM>>>();
    mgemm_v<<<dim3(KH / 128, M_ / 128), 256, MG_SMEM>>>();

    qnorm_rope<<<M_, 256>>>();
    knorm_rope<<<M_, 128>>>();
    split_v<<<M_ * KH / 4 / 256, 256>>>();

    attn_tc<<<dim3(T_ / 128, NHEAD, B_), 256, AT_SMEM>>>();

    mgemm_o<<<dim3(C_ / 128, M_ / 128), 256, MG_SMEM>>>(out);
}